// round 13
// baseline (speedup 1.0000x reference)
#include <cuda_runtime.h>
#include <cuda_fp16.h>
#include <math.h>
#include <stdint.h>

#define BB    4
#define NTOT  16384
#define CC    256
#define NHH   8
#define HDD   32
#define NKV   1024
#define KCONV 4096
#define TQ    16384
#define SCALE 0.17677669529663689f
#define C2E   0.25503486963f   // SCALE * log2(e)

// GEMM tiles: BM=64, BN=64, BK=32; smem row stride 40 halves (80 B)
#define ABYTES 5120
#define BBYTES 5120
#define BUF1   (ABYTES + BBYTES)        // 10240
#define SMEM1  (2*BUF1)
#define BUF2   (ABYTES + 2*BBYTES)      // 15360
#define SMEM2  (2*BUF2)

// ---------------- scratch (device globals) ----------------
__device__ __half g_xh16[BB*NTOT*CC];            // x fp16
__device__ __half g_qh16[TQ*CC];                 // q input fp16
__device__ __half g_wqh [CC*CC];
__device__ __half g_wkvh[CC*2*CC];
__device__ __half g_pwh [CC*CC],  g_pwl[CC*CC];
__device__ __half g_wsrh[KCONV*CC];
__device__ float  g_xr [BB*NKV*CC];              // conv out fp32 (LN stats)
__device__ __half g_xrh[BB*NKV*CC];              // LN'd fp16
__device__ __half g_kh [BB*NHH*NKV*HDD], g_vh[BB*NHH*NKV*HDD];
__device__ __half g_qhh[TQ*CC];                  // projected q fp16
__device__ __half g_ohh[TQ*CC];                  // attention out fp16

// ---------------- helpers ----------------
__device__ __forceinline__ void fsplit(float x, __half& h, __half& l) {
    h = __float2half_rn(x);
    l = __float2half_rn(x - __half2float(h));
}

__device__ __forceinline__ void mma16816(float* c,
    uint32_t a0, uint32_t a1, uint32_t a2, uint32_t a3, uint32_t b0, uint32_t b1) {
    asm volatile("mma.sync.aligned.m16n8k16.row.col.f32.f16.f16.f32 "
        "{%0,%1,%2,%3}, {%4,%5,%6,%7}, {%8,%9}, {%0,%1,%2,%3};\n"
        : "+f"(c[0]), "+f"(c[1]), "+f"(c[2]), "+f"(c[3])
        : "r"(a0), "r"(a1), "r"(a2), "r"(a3), "r"(b0), "r"(b1));
}

__device__ __forceinline__ void ldsm4(uint32_t& r0, uint32_t& r1, uint32_t& r2,
                                      uint32_t& r3, uint32_t addr) {
    asm volatile("ldmatrix.sync.aligned.m8n8.x4.shared.b16 {%0,%1,%2,%3}, [%4];"
        : "=r"(r0), "=r"(r1), "=r"(r2), "=r"(r3) : "r"(addr));
}

__device__ __forceinline__ uint32_t pack2(__half lo, __half hi) {
    __half2 t = __halves2half2(lo, hi);
    return *(uint32_t*)&t;
}

// ---------------- convert kernels ----------------
__global__ void k_cvt(const float* __restrict__ src, __half* __restrict__ dh, int n) {
    int i = blockIdx.x * 256 + threadIdx.x;
    if (i < n) dh[i] = __float2half_rn(src[i]);
}

__global__ void k_split(const float* __restrict__ src, __half* __restrict__ dh,
                        __half* __restrict__ dl, int n) {
    int i = blockIdx.x * 256 + threadIdx.x;
    if (i < n) { __half h, l; fsplit(src[i], h, l); dh[i] = h; dl[i] = l; }
}

__global__ void k_cvt_srw(const float* __restrict__ srw) {
    int idx = blockIdx.x * 256 + threadIdx.x;
    if (idx >= KCONV * CC) return;
    int co = idx & 255;
    int k  = idx >> 8;
    int ci = k & 255;
    int p  = k >> 8;
    g_wsrh[idx] = __float2half_rn(srw[(size_t)co * KCONV + ci * 16 + p]);
}

// ---------------- loaders (BM=64, BN=64, BK=32; stride 40 halves) ----------------
__device__ __forceinline__ void gload_A16(const __half* __restrict__ A, int K,
                                          int m0, int k0, uint32_t rA[4]) {
    int tid = threadIdx.x;
    #pragma unroll
    for (int i = 0; i < 4; i++) {
        int l = tid + i * 256;
        int m = l >> 4, kp = l & 15;
        rA[i] = *(const uint32_t*)(A + (size_t)(m0 + m) * K + k0 + kp * 2);
    }
}

__device__ __forceinline__ void gstore_A16(const uint32_t rA[4], __half* Ash) {
    int tid = threadIdx.x;
    #pragma unroll
    for (int i = 0; i < 4; i++) {
        int l = tid + i * 256;
        int m = l >> 4, kp = l & 15;
        ((uint32_t*)Ash)[m * 20 + kp] = rA[i];
    }
}

__device__ __forceinline__ void gload_B1(const __half* __restrict__ Bh,
                                         int N, int k0, int n0, __half rBh[8]) {
    int tid = threadIdx.x;
    #pragma unroll
    for (int i = 0; i < 8; i++) {
        int l = tid + i * 256;
        int kk = l >> 6, n = l & 63;
        rBh[i] = Bh[(size_t)(k0 + kk) * N + n0 + n];
    }
}

__device__ __forceinline__ void gstore_B1(const __half rBh[8], __half* Bsh) {
    int tid = threadIdx.x;
    #pragma unroll
    for (int i = 0; i < 8; i++) {
        int l = tid + i * 256;
        int kk = l >> 6, n = l & 63;
        Bsh[n * 40 + kk] = rBh[i];
    }
}

__device__ __forceinline__ void gload_B2(const __half* __restrict__ Bh,
                                         const __half* __restrict__ Bl,
                                         int N, int k0, int n0,
                                         __half rBh[8], __half rBl[8]) {
    int tid = threadIdx.x;
    #pragma unroll
    for (int i = 0; i < 8; i++) {
        int l = tid + i * 256;
        int kk = l >> 6, n = l & 63;
        size_t g = (size_t)(k0 + kk) * N + n0 + n;
        rBh[i] = Bh[g];
        rBl[i] = Bl[g];
    }
}

__device__ __forceinline__ void gstore_B2(const __half rBh[8], const __half rBl[8],
                                          __half* Bsh, __half* Bsl) {
    int tid = threadIdx.x;
    #pragma unroll
    for (int i = 0; i < 8; i++) {
        int l = tid + i * 256;
        int kk = l >> 6, n = l & 63;
        Bsh[n * 40 + kk] = rBh[i];
        Bsl[n * 40 + kk] = rBl[i];
    }
}

// conv A gather (fp16 x)
__device__ __forceinline__ void conv_load_A16(const __half* __restrict__ x,
                                              int m0, int k0, uint32_t rA[4]) {
    int tid = threadIdx.x;
    int p = k0 >> 8, cib = k0 & 255;
    int kh = p >> 2, kw = p & 3;
    #pragma unroll
    for (int i = 0; i < 4; i++) {
        int l = tid + i * 256;
        int m = l >> 4, kp = l & 15;
        int mm = m0 + m;
        int b = mm >> 10, rem = mm & 1023, oh = rem >> 5, ow = rem & 31;
        size_t g = ((size_t)(b * NTOT + (oh * 4 + kh) * 128 + ow * 4 + kw)) * CC + cib + kp * 2;
        rA[i] = *(const uint32_t*)(x + g);
    }
}

// ---------------- mma steps (one BK=32), warp tile 16x32 ----------------
__device__ __forceinline__ void mma_step1(uint32_t aU, uint32_t bU,
                                          float acc[4][4], int wm, int wn,
                                          int aOff, int bOff) {
    #pragma unroll
    for (int kc = 0; kc < 2; kc++) {
        int cB = kc * 32;
        uint32_t a[4], bh[4][2];
        ldsm4(a[0], a[1], a[2], a[3], aU + (wm * 16) * 80 + cB + aOff);
        #pragma unroll
        for (int pp = 0; pp < 2; pp++) {
            uint32_t base = (wn * 32 + pp * 16) * 80 + cB;
            ldsm4(bh[2*pp][0], bh[2*pp][1], bh[2*pp+1][0], bh[2*pp+1][1], bU + base + bOff);
        }
        #pragma unroll
        for (int nt = 0; nt < 4; nt++)
            mma16816(acc[nt], a[0], a[1], a[2], a[3], bh[nt][0], bh[nt][1]);
    }
}

__device__ __forceinline__ void mma_step2(uint32_t aU, uint32_t bhU, uint32_t blU,
                                          float acc[4][4], int wm, int wn,
                                          int aOff, int bOff) {
    #pragma unroll
    for (int kc = 0; kc < 2; kc++) {
        int cB = kc * 32;
        uint32_t a[4], bh[4][2], bl[4][2];
        ldsm4(a[0], a[1], a[2], a[3], aU + (wm * 16) * 80 + cB + aOff);
        #pragma unroll
        for (int pp = 0; pp < 2; pp++) {
            uint32_t base = (wn * 32 + pp * 16) * 80 + cB;
            ldsm4(bh[2*pp][0], bh[2*pp][1], bh[2*pp+1][0], bh[2*pp+1][1], bhU + base + bOff);
            ldsm4(bl[2*pp][0], bl[2*pp][1], bl[2*pp+1][0], bl[2*pp+1][1], blU + base + bOff);
        }
        #pragma unroll
        for (int nt = 0; nt < 4; nt++) {
            mma16816(acc[nt], a[0], a[1], a[2], a[3], bh[nt][0], bh[nt][1]);
            mma16816(acc[nt], a[0], a[1], a[2], a[3], bl[nt][0], bl[nt][1]);
        }
    }
}

#define GEMM_PROLOG \
    extern __shared__ __align__(16) unsigned char smraw[]; \
    int tid = threadIdx.x; \
    int w = tid >> 5, lane = tid & 31; \
    int gid = lane >> 2, tig = lane & 3; \
    int rr = lane & 7, qq = lane >> 3; \
    int wm = w & 3, wn = w >> 2; \
    uint32_t smemU = (uint32_t)__cvta_generic_to_shared(smraw); \
    int aOff = (rr + (qq & 1) * 8) * 80 + ((qq >> 1) * 8) * 2; \
    int bOff = (rr + (qq >> 1) * 8) * 80 + ((qq & 1) * 8) * 2; \
    (void)gid; (void)tig; \
    float acc[4][4]; \
    _Pragma("unroll") for (int j = 0; j < 4; j++) \
    _Pragma("unroll") for (int t = 0; t < 4; t++) acc[j][t] = 0.f;

// ---------------- conv-as-GEMM: M=4096, K=4096, N=256 ----------------
__global__ void __launch_bounds__(256) k_conv_mma(const float* __restrict__ srb) {
    GEMM_PROLOG
    int n0 = blockIdx.x * 64, m0 = blockIdx.y * 64;
    uint32_t rA[4]; __half rBh[8];
    conv_load_A16(g_xh16, m0, 0, rA);
    gload_B1(g_wsrh, CC, 0, n0, rBh);
    gstore_A16(rA, (__half*)smraw);
    gstore_B1(rBh, (__half*)(smraw + ABYTES));
    for (int k0 = 0; k0 < KCONV; k0 += 32) {
        int cur = (k0 >> 5) & 1;
        __syncthreads();
        bool more = (k0 + 32 < KCONV);
        if (more) {
            conv_load_A16(g_xh16, m0, k0 + 32, rA);
            gload_B1(g_wsrh, CC, k0 + 32, n0, rBh);
        }
        uint32_t bu = smemU + cur * BUF1;
        mma_step1(bu, bu + ABYTES, acc, wm, wn, aOff, bOff);
        if (more) {
            gstore_A16(rA, (__half*)(smraw + (cur ^ 1) * BUF1));
            gstore_B1(rBh, (__half*)(smraw + (cur ^ 1) * BUF1 + ABYTES));
        }
    }
    #pragma unroll
    for (int nt = 0; nt < 4; nt++) {
        int r0 = m0 + wm * 16 + gid;
        int cb = n0 + wn * 32 + nt * 8 + tig * 2;
        g_xr[(size_t)r0 * CC + cb]       = acc[nt][0] + srb[cb];
        g_xr[(size_t)r0 * CC + cb + 1]   = acc[nt][1] + srb[cb + 1];
        g_xr[(size_t)(r0+8) * CC + cb]   = acc[nt][2] + srb[cb];
        g_xr[(size_t)(r0+8) * CC + cb+1] = acc[nt][3] + srb[cb + 1];
    }
}

// ---------------- LayerNorm: g_xr (fp32) -> g_xrh (fp16) ----------------
__global__ void __launch_bounds__(256) k_layernorm(const float* __restrict__ gamma,
                                                   const float* __restrict__ beta) {
    int row  = blockIdx.x * 8 + (threadIdx.x >> 5);
    int lane = threadIdx.x & 31;
    const float* xr = g_xr + (size_t)row * CC;
    __half* xo = g_xrh + (size_t)row * CC;
    float v[8], s = 0.f;
    #pragma unroll
    for (int i = 0; i < 8; i++) { v[i] = xr[lane + i * 32]; s += v[i]; }
    #pragma unroll
    for (int o = 16; o; o >>= 1) s += __shfl_xor_sync(0xffffffffu, s, o);
    float mu = s * (1.f / 256.f), s2 = 0.f;
    #pragma unroll
    for (int i = 0; i < 8; i++) { float d = v[i] - mu; s2 += d * d; }
    #pragma unroll
    for (int o = 16; o; o >>= 1) s2 += __shfl_xor_sync(0xffffffffu, s2, o);
    float rstd = rsqrtf(s2 * (1.f / 256.f) + 1e-5f);
    #pragma unroll
    for (int i = 0; i < 8; i++) {
        int c = lane + i * 32;
        xo[c] = __float2half_rn((v[i] - mu) * rstd * gamma[c] + beta[c]);
    }
}

// ---------------- KV projection: M=4096, K=256, N=512 ----------------
__global__ void __launch_bounds__(256) k_kv_mma() {
    GEMM_PROLOG
    int n0 = blockIdx.x * 64, m0 = blockIdx.y * 64;
    uint32_t rA[4]; __half rBh[8];
    gload_A16(g_xrh, CC, m0, 0, rA);
    gload_B1(g_wkvh, 2 * CC, 0, n0, rBh);
    gstore_A16(rA, (__half*)smraw);
    gstore_B1(rBh, (__half*)(smraw + ABYTES));
    for (int k0 = 0; k0 < CC; k0 += 32) {
        int cur = (k0 >> 5) & 1;
        __syncthreads();
        bool more = (k0 + 32 < CC);
        if (more) {
            gload_A16(g_xrh, CC, m0, k0 + 32, rA);
            gload_B1(g_wkvh, 2 * CC, k0 + 32, n0, rBh);
        }
        uint32_t bu = smemU + cur * BUF1;
        mma_step1(bu, bu + ABYTES, acc, wm, wn, aOff, bOff);
        if (more) {
            gstore_A16(rA, (__half*)(smraw + (cur ^ 1) * BUF1));
            gstore_B1(rBh, (__half*)(smraw + (cur ^ 1) * BUF1 + ABYTES));
        }
    }
    #pragma unroll
    for (int nt = 0; nt < 4; nt++)
        #pragma unroll
        for (int e = 0; e < 4; e++) {
            int r = m0 + wm * 16 + gid + (e >= 2 ? 8 : 0);
            int n = n0 + wn * 32 + nt * 8 + tig * 2 + (e & 1);
            int b = r >> 10, pos = r & 1023;
            int half = n >> 8, hh = (n >> 5) & 7, d = n & 31;
            size_t dst = ((size_t)((b * NHH + hh) * NKV + pos)) * HDD + d;
            __half v = __float2half_rn(acc[nt][e]);
            if (half == 0) g_kh[dst] = v; else g_vh[dst] = v;
        }
}

// ---------------- Q projection: M=16384, K=256, N=256 ----------------
__global__ void __launch_bounds__(256) k_qproj_mma() {
    GEMM_PROLOG
    int n0 = blockIdx.x * 64, m0 = blockIdx.y * 64;
    uint32_t rA[4]; __half rBh[8];
    gload_A16(g_qh16, CC, m0, 0, rA);
    gload_B1(g_wqh, CC, 0, n0, rBh);
    gstore_A16(rA, (__half*)smraw);
    gstore_B1(rBh, (__half*)(smraw + ABYTES));
    for (int k0 = 0; k0 < CC; k0 += 32) {
        int cur = (k0 >> 5) & 1;
        __syncthreads();
        bool more = (k0 + 32 < CC);
        if (more) {
            gload_A16(g_qh16, CC, m0, k0 + 32, rA);
            gload_B1(g_wqh, CC, k0 + 32, n0, rBh);
        }
        uint32_t bu = smemU + cur * BUF1;
        mma_step1(bu, bu + ABYTES, acc, wm, wn, aOff, bOff);
        if (more) {
            gstore_A16(rA, (__half*)(smraw + (cur ^ 1) * BUF1));
            gstore_B1(rBh, (__half*)(smraw + (cur ^ 1) * BUF1 + ABYTES));
        }
    }
    #pragma unroll
    for (int nt = 0; nt < 4; nt++)
        #pragma unroll
        for (int e = 0; e < 4; e++) {
            int r = m0 + wm * 16 + gid + (e >= 2 ? 8 : 0);
            int n = n0 + wn * 32 + nt * 8 + tig * 2 + (e & 1);
            g_qhh[(size_t)r * CC + n] = __float2half_rn(acc[nt][e]);
        }
}

// ---------------- Output projection: M=16384, K=256, N=256 (split-B) ----------------
__global__ void __launch_bounds__(256) k_proj_mma(const float* __restrict__ bp,
                                                  float* __restrict__ out) {
    GEMM_PROLOG
    int n0 = blockIdx.x * 64, m0 = blockIdx.y * 64;
    uint32_t rA[4]; __half rBh[8], rBl[8];
    gload_A16(g_ohh, CC, m0, 0, rA);
    gload_B2(g_pwh, g_pwl, CC, 0, n0, rBh, rBl);
    gstore_A16(rA, (__half*)smraw);
    gstore_B2(rBh, rBl, (__half*)(smraw + ABYTES), (__half*)(smraw + ABYTES + BBYTES));
    for (int k0 = 0; k0 < CC; k0 += 32) {
        int cur = (k0 >> 5) & 1;
        __syncthreads();
        bool more = (k0 + 32 < CC);
        if (more) {
            gload_A16(g_ohh, CC, m0, k0 + 32, rA);
            gload_B2(g_pwh, g_pwl, CC, k0 + 32, n0, rBh, rBl);
        }
        uint32_t bu = smemU + cur * BUF2;
        mma_step2(bu, bu + ABYTES, bu + ABYTES + BBYTES, acc, wm, wn, aOff, bOff);
        if (more) {
            gstore_A16(rA, (__half*)(smraw + (cur ^ 1) * BUF2));
            gstore_B2(rBh, rBl, (__half*)(smraw + (cur ^ 1) * BUF2 + ABYTES),
                      (__half*)(smraw + (cur ^ 1) * BUF2 + ABYTES + BBYTES));
        }
    }
    #pragma unroll
    for (int nt = 0; nt < 4; nt++)
        #pragma unroll
        for (int e = 0; e < 4; e++) {
            int r = m0 + wm * 16 + gid + (e >= 2 ? 8 : 0);
            int n = n0 + wn * 32 + nt * 8 + tig * 2 + (e & 1);
            out[(size_t)r * CC + n] = acc[nt][e] + bp[n];
        }
}

// ---------------- Flash attention (R11 core; fp16 output epilogue) ----------------
#define VT_S 130

__global__ void __launch_bounds__(256) k_attn_flash(const int* __restrict__ qlen) {
    __shared__ __half Ks[128 * 40];
    __shared__ __half Vt[32 * VT_S];

    int tid = threadIdx.x;
    int w = tid >> 5, lane = tid & 31;
    int gid = lane >> 2, tig = lane & 3;
    int h = blockIdx.y;
    int q0 = blockIdx.x * 128;

    int l0 = qlen[0], l1 = qlen[1], l2 = qlen[2];
    int b = 0;
    if (q0 >= l0) b = 1;
    if (q0 >= l0 + l1) b = 2;
    if (q0 >= l0 + l1 + l2) b = 3;

    const __half* Kb = g_kh + ((size_t)(b * NHH + h) * NKV) * HDD;
    const __half* Vb = g_vh + ((size_t)(b * NHH + h) * NKV) * HDD;

    uint32_t aQ[2][4];
    {
        const __half* Qp = g_qhh + (size_t)(q0 + w * 16) * CC + h * HDD;
        #pragma unroll
        for (int kc = 0; kc < 2; kc++) {
            int c = kc * 16 + tig * 2;
            aQ[kc][0] = *(const uint32_t*)(Qp + (size_t)gid * CC + c);
            aQ[kc][1] = *(const uint32_t*)(Qp + (size_t)(gid + 8) * CC + c);
            aQ[kc][2] = *(const uint32_t*)(Qp + (size_t)gid * CC + c + 8);
            aQ[kc][3] = *(const uint32_t*)(Qp + (size_t)(gid + 8) * CC + c + 8);
        }
    }

    float o[4][4];
    #pragma unroll
    for (int i = 0; i < 4; i++)
        #pragma unroll
        for (int j = 0; j < 4; j++) o[i][j] = 0.f;
    float mrow[2] = {-1e30f, -1e30f};
    float lsum[2] = {0.f, 0.f};

    for (int kt = 0; kt < 8; kt++) {
        #pragma unroll
        for (int i = 0; i < 8; i++) {
            int idx = tid + i * 256;
            int key = idx >> 4, dp = idx & 15;
            ((uint32_t*)Ks)[key * 20 + dp] =
                *(const uint32_t*)(Kb + (size_t)(kt * 128 + key) * HDD + dp * 2);
        }
        #pragma unroll
        for (int i = 0; i < 8; i++) {
            int idx = tid + i * 256;
            int key = idx >> 4, dp = idx & 15;
            uint32_t u = *(const uint32_t*)(Vb + (size_t)(kt * 128 + key) * HDD + dp * 2);
            __half2 h2 = *(__half2*)&u;
            Vt[(dp * 2) * VT_S + key]     = __low2half(h2);
            Vt[(dp * 2 + 1) * VT_S + key] = __high2half(h2);
        }
        __syncthreads();

        float c[16][4];
        #pragma unroll
        for (int t = 0; t < 16; t++) {
            c[t][0] = c[t][1] = c[t][2] = c[t][3] = 0.f;
            #pragma unroll
            for (int kc = 0; kc < 2; kc++) {
                int cc = kc * 16 + tig * 2;
                uint32_t b0 = *(const uint32_t*)(Ks + (t * 8 + gid) * 40 + cc);
                uint32_t b1 = *(const uint32_t*)(Ks + (t * 8 + gid) * 40 + cc + 8);
                mma16816(c[t], aQ[kc][0], aQ[kc][1], aQ[kc][2], aQ[kc][3], b0, b1);
            }
        }

        float tm0 = -1e30f, tm1 = -1e30f;
        #pragma unroll
        for (int t = 0; t < 16; t++) {
            tm0 = fmaxf(tm0, fmaxf(c[t][0], c[t][1]));
            tm1 = fmaxf(tm1, fmaxf(c[t][2], c[t][3]));
        }
        tm0 = fmaxf(tm0, __shfl_xor_sync(0xffffffffu, tm0, 1));
        tm0 = fmaxf(tm0, __shfl_xor_sync(0xffffffffu, tm0, 2));
        tm1 = fmaxf(tm1, __shfl_xor_sync(0xffffffffu, tm1, 1));
        tm1 = fmaxf(tm1, __shfl_xor_sync(0xffffffffu, tm1, 2));
        float mn0 = fmaxf(mrow[0], tm0);
        float mn1 = fmaxf(mrow[1], tm1);
        float f0 = exp2f((mrow[0] - mn0) * C2E);
        float f1 = exp2f((mrow[1] - mn1) * C2E);
        mrow[0] = mn0; mrow[1] = mn1;
        lsum[0] *= f0; lsum[1] *= f1;
        #pragma unroll
        for (int nt = 0; nt < 4; nt++) {
            o[nt][0] *= f0; o[nt][1] *= f0;
            o[nt][2] *= f1; o[nt][3] *= f1;
        }
        float ps0 = 0.f, ps1 = 0.f;
        uint32_t pf[16][2];
        #pragma unroll
        for (int t = 0; t < 16; t++) {
            float p0 = exp2f((c[t][0] - mn0) * C2E);
            float p1 = exp2f((c[t][1] - mn0) * C2E);
            float p2 = exp2f((c[t][2] - mn1) * C2E);
            float p3 = exp2f((c[t][3] - mn1) * C2E);
            ps0 += p0 + p1;
            ps1 += p2 + p3;
            pf[t][0] = pack2(__float2half_rn(p0), __float2half_rn(p1));
            pf[t][1] = pack2(__float2half_rn(p2), __float2half_rn(p3));
        }
        lsum[0] += ps0;
        lsum[1] += ps1;

        #pragma unroll
        for (int j = 0; j < 8; j++) {
            uint32_t a0 = pf[2 * j][0];
            uint32_t a1 = pf[2 * j][1];
            uint32_t a2 = pf[2 * j + 1][0];
            uint32_t a3 = pf[2 * j + 1][1];
            #pragma unroll
            for (int nt = 0; nt < 4; nt++) {
                int d = nt * 8 + gid;
                uint32_t b0 = *(const uint32_t*)(Vt + d * VT_S + 16 * j + tig * 2);
                uint32_t b1 = *(const uint32_t*)(Vt + d * VT_S + 16 * j + tig * 2 + 8);
                mma16816(o[nt], a0, a1, a2, a3, b0, b1);
            }
        }
        __syncthreads();
    }

    lsum[0] += __shfl_xor_sync(0xffffffffu, lsum[0], 1);
    lsum[0] += __shfl_xor_sync(0xffffffffu, lsum[0], 2);
    lsum[1] += __shfl_xor_sync(0xffffffffu, lsum[1], 1);
    lsum[1] += __shfl_xor_sync(0xffffffffu, lsum[1], 2);

    float i0 = 1.f / lsum[0], i1 = 1.f / lsum[1];
    __half* Op = g_ohh + (size_t)(q0 + w * 16) * CC + h * HDD;
    #pragma unroll
    for (int nt = 0; nt < 4; nt++) {
        int col = nt * 8 + tig * 2;
        *(uint32_t*)(Op + (size_t)gid * CC + col) =
            pack2(__float2half_rn(o[nt][0] * i0), __float2half_rn(o[nt][1] * i0));
        *(uint32_t*)(Op + (size_t)(gid + 8) * CC + col) =
            pack2(__float2half_rn(o[nt][2] * i1), __float2half_rn(o[nt][3] * i1));
    }
}

// ---------------- launch ----------------
extern "C" void kernel_launch(void* const* d_in, const int* in_sizes, int n_in,
                              void* d_out, int out_size) {
    const float* x      = (const float*)d_in[0];
    const float* q      = (const float*)d_in[1];
    const int*   qlen   = (const int*)  d_in[4];
    const float* w_q    = (const float*)d_in[5];
    const float* w_kv   = (const float*)d_in[6];
    const float* sr_w   = (const float*)d_in[7];
    const float* sr_b   = (const float*)d_in[8];
    const float* ln_g   = (const float*)d_in[9];
    const float* ln_b   = (const float*)d_in[10];
    const float* proj_w = (const float*)d_in[11];
    const float* proj_b = (const float*)d_in[12];
    float* out = (float*)d_out;

    cudaFuncSetAttribute(k_conv_mma,  cudaFuncAttributeMaxDynamicSharedMemorySize, SMEM1);
    cudaFuncSetAttribute(k_kv_mma,    cudaFuncAttributeMaxDynamicSharedMemorySize, SMEM1);
    cudaFuncSetAttribute(k_qproj_mma, cudaFuncAttributeMaxDynamicSharedMemorySize, SMEM1);
    cudaFuncSetAttribute(k_proj_mma,  cudaFuncAttributeMaxDynamicSharedMemorySize, SMEM2);

    __half *xh16, *qh16, *wqh, *wkvh, *pwh, *pwl;
    cudaGetSymbolAddress((void**)&xh16, g_xh16);
    cudaGetSymbolAddress((void**)&qh16, g_qh16);
    cudaGetSymbolAddress((void**)&wqh,  g_wqh);
    cudaGetSymbolAddress((void**)&wkvh, g_wkvh);
    cudaGetSymbolAddress((void**)&pwh,  g_pwh);
    cudaGetSymbolAddress((void**)&pwl,  g_pwl);

    k_cvt<<<(BB*NTOT*CC + 255)/256, 256>>>(x, xh16, BB*NTOT*CC);
    k_cvt<<<(TQ*CC + 255)/256, 256>>>(q, qh16, TQ*CC);
    k_cvt<<<(CC*CC + 255)/256, 256>>>(w_q, wqh, CC*CC);
    k_cvt<<<(CC*2*CC + 255)/256, 256>>>(w_kv, wkvh, CC*2*CC);
    k_split<<<(CC*CC + 255)/256, 256>>>(proj_w, pwh, pwl, CC*CC);
    k_cvt_srw<<<(KCONV*CC + 255)/256, 256>>>(sr_w);

    k_conv_mma<<<dim3(CC/64, (BB*NKV)/64), 256, SMEM1>>>(sr_b);
    k_layernorm<<<(BB*NKV)/8, 256>>>(ln_g, ln_b);
    k_kv_mma<<<dim3((2*CC)/64, (BB*NKV)/64), 256, SMEM1>>>();
    k_qproj_mma<<<dim3(CC/64, TQ/64), 256, SMEM1>>>();
    k_attn_flash<<<dim3(TQ/128, NHH), 256>>>(qlen);
    k_proj_mma<<<dim3(CC/64, TQ/64), 256, SMEM2>>>(proj_b, out);
}

// round 14
// speedup vs baseline: 1.0552x; 1.0552x over previous
#include <cuda_runtime.h>
#include <cuda_fp16.h>
#include <math.h>
#include <stdint.h>

#define BB    4
#define NTOT  16384
#define CC    256
#define NHH   8
#define HDD   32
#define NKV   1024
#define KCONV 4096
#define TQ    16384
#define SCALE 0.17677669529663689f
#define C2E   0.25503486963f   // SCALE * log2(e)

// GEMM tiles: BM=64, BN=64, BK=32; smem row stride 40 halves (80 B)
#define ABYTES 5120
#define BBYTES 5120
#define BUF1   (ABYTES + BBYTES)        // 10240
#define SMEM1  (2*BUF1)
#define BUF2   (ABYTES + 2*BBYTES)      // 15360
#define SMEM2  (2*BUF2)

// ---------------- scratch (device globals) ----------------
__device__ __half g_wqh [CC*CC];
__device__ __half g_wkvh[CC*2*CC];
__device__ __half g_pwh [CC*CC],  g_pwl[CC*CC];
__device__ __half g_wsrh[KCONV*CC];
__device__ float  g_xr [BB*NKV*CC];
__device__ __half g_kh [BB*NHH*NKV*HDD], g_vh[BB*NHH*NKV*HDD];
__device__ __half g_qhh[TQ*CC];
__device__ float  g_o  [TQ*CC];

// ---------------- helpers ----------------
__device__ __forceinline__ void fsplit(float x, __half& h, __half& l) {
    h = __float2half_rn(x);
    l = __float2half_rn(x - __half2float(h));
}

__device__ __forceinline__ void mma16816(float* c,
    uint32_t a0, uint32_t a1, uint32_t a2, uint32_t a3, uint32_t b0, uint32_t b1) {
    asm volatile("mma.sync.aligned.m16n8k16.row.col.f32.f16.f16.f32 "
        "{%0,%1,%2,%3}, {%4,%5,%6,%7}, {%8,%9}, {%0,%1,%2,%3};\n"
        : "+f"(c[0]), "+f"(c[1]), "+f"(c[2]), "+f"(c[3])
        : "r"(a0), "r"(a1), "r"(a2), "r"(a3), "r"(b0), "r"(b1));
}

__device__ __forceinline__ void ldsm4(uint32_t& r0, uint32_t& r1, uint32_t& r2,
                                      uint32_t& r3, uint32_t addr) {
    asm volatile("ldmatrix.sync.aligned.m8n8.x4.shared.b16 {%0,%1,%2,%3}, [%4];"
        : "=r"(r0), "=r"(r1), "=r"(r2), "=r"(r3) : "r"(addr));
}

__device__ __forceinline__ uint32_t pack2(__half lo, __half hi) {
    __half2 t = __halves2half2(lo, hi);
    return *(uint32_t*)&t;
}

// ---------------- weight convert kernels ----------------
__global__ void k_cvt(const float* __restrict__ src, __half* __restrict__ dh, int n) {
    int i = blockIdx.x * 256 + threadIdx.x;
    if (i < n) dh[i] = __float2half_rn(src[i]);
}

__global__ void k_split(const float* __restrict__ src, __half* __restrict__ dh,
                        __half* __restrict__ dl, int n) {
    int i = blockIdx.x * 256 + threadIdx.x;
    if (i < n) { __half h, l; fsplit(src[i], h, l); dh[i] = h; dl[i] = l; }
}

__global__ void k_cvt_srw(const float* __restrict__ srw) {
    int idx = blockIdx.x * 256 + threadIdx.x;
    if (idx >= KCONV * CC) return;
    int co = idx & 255;
    int k  = idx >> 8;
    int ci = k & 255;
    int p  = k >> 8;
    g_wsrh[idx] = __float2half_rn(srw[(size_t)co * KCONV + ci * 16 + p]);
}

// ---------------- loaders (BM=64, BN=64, BK=32; stride 40 halves) ----------------
__device__ __forceinline__ void gload_A(const float* __restrict__ A, int K,
                                        int m0, int k0, float2 rA[4]) {
    int tid = threadIdx.x;
    #pragma unroll
    for (int i = 0; i < 4; i++) {
        int l = tid + i * 256;
        int m = l >> 4, kp = l & 15;
        rA[i] = *(const float2*)(A + (size_t)(m0 + m) * K + k0 + kp * 2);
    }
}

__device__ __forceinline__ void gstore_A(const float2 rA[4], __half* Ash) {
    int tid = threadIdx.x;
    #pragma unroll
    for (int i = 0; i < 4; i++) {
        int l = tid + i * 256;
        int m = l >> 4, kp = l & 15;
        ((uint32_t*)Ash)[m * 20 + kp] =
            pack2(__float2half_rn(rA[i].x), __float2half_rn(rA[i].y));
    }
}

__device__ __forceinline__ void gload_B1(const __half* __restrict__ Bh,
                                         int N, int k0, int n0, __half rBh[8]) {
    int tid = threadIdx.x;
    #pragma unroll
    for (int i = 0; i < 8; i++) {
        int l = tid + i * 256;
        int kk = l >> 6, n = l & 63;
        rBh[i] = Bh[(size_t)(k0 + kk) * N + n0 + n];
    }
}

__device__ __forceinline__ void gstore_B1(const __half rBh[8], __half* Bsh) {
    int tid = threadIdx.x;
    #pragma unroll
    for (int i = 0; i < 8; i++) {
        int l = tid + i * 256;
        int kk = l >> 6, n = l & 63;
        Bsh[n * 40 + kk] = rBh[i];
    }
}

__device__ __forceinline__ void gload_B2(const __half* __restrict__ Bh,
                                         const __half* __restrict__ Bl,
                                         int N, int k0, int n0,
                                         __half rBh[8], __half rBl[8]) {
    int tid = threadIdx.x;
    #pragma unroll
    for (int i = 0; i < 8; i++) {
        int l = tid + i * 256;
        int kk = l >> 6, n = l & 63;
        size_t g = (size_t)(k0 + kk) * N + n0 + n;
        rBh[i] = Bh[g];
        rBl[i] = Bl[g];
    }
}

__device__ __forceinline__ void gstore_B2(const __half rBh[8], const __half rBl[8],
                                          __half* Bsh, __half* Bsl) {
    int tid = threadIdx.x;
    #pragma unroll
    for (int i = 0; i < 8; i++) {
        int l = tid + i * 256;
        int kk = l >> 6, n = l & 63;
        Bsh[n * 40 + kk] = rBh[i];
        Bsl[n * 40 + kk] = rBl[i];
    }
}

// conv A gather loader (x fp32, NCHW-gathered); BM=64
__device__ __forceinline__ void conv_load_A(const float* __restrict__ x,
                                            int m0, int k0, float2 rA[4]) {
    int tid = threadIdx.x;
    int p = k0 >> 8, cib = k0 & 255;
    int kh = p >> 2, kw = p & 3;
    #pragma unroll
    for (int i = 0; i < 4; i++) {
        int l = tid + i * 256;
        int m = l >> 4, kp = l & 15;
        int mm = m0 + m;
        int b = mm >> 10, rem = mm & 1023, oh = rem >> 5, ow = rem & 31;
        size_t g = ((size_t)(b * NTOT + (oh * 4 + kh) * 128 + ow * 4 + kw)) * CC + cib + kp * 2;
        rA[i] = *(const float2*)(x + g);
    }
}

// ---------------- mma steps (one BK=32), warp tile 16x32 ----------------
__device__ __forceinline__ void mma_step1(uint32_t aU, uint32_t bU,
                                          float acc[4][4], int wm, int wn,
                                          int aOff, int bOff) {
    #pragma unroll
    for (int kc = 0; kc < 2; kc++) {
        int cB = kc * 32;
        uint32_t a[4], bh[4][2];
        ldsm4(a[0], a[1], a[2], a[3], aU + (wm * 16) * 80 + cB + aOff);
        #pragma unroll
        for (int pp = 0; pp < 2; pp++) {
            uint32_t base = (wn * 32 + pp * 16) * 80 + cB;
            ldsm4(bh[2*pp][0], bh[2*pp][1], bh[2*pp+1][0], bh[2*pp+1][1], bU + base + bOff);
        }
        #pragma unroll
        for (int nt = 0; nt < 4; nt++)
            mma16816(acc[nt], a[0], a[1], a[2], a[3], bh[nt][0], bh[nt][1]);
    }
}

__device__ __forceinline__ void mma_step2(uint32_t aU, uint32_t bhU, uint32_t blU,
                                          float acc[4][4], int wm, int wn,
                                          int aOff, int bOff) {
    #pragma unroll
    for (int kc = 0; kc < 2; kc++) {
        int cB = kc * 32;
        uint32_t a[4], bh[4][2], bl[4][2];
        ldsm4(a[0], a[1], a[2], a[3], aU + (wm * 16) * 80 + cB + aOff);
        #pragma unroll
        for (int pp = 0; pp < 2; pp++) {
            uint32_t base = (wn * 32 + pp * 16) * 80 + cB;
            ldsm4(bh[2*pp][0], bh[2*pp][1], bh[2*pp+1][0], bh[2*pp+1][1], bhU + base + bOff);
            ldsm4(bl[2*pp][0], bl[2*pp][1], bl[2*pp+1][0], bl[2*pp+1][1], blU + base + bOff);
        }
        #pragma unroll
        for (int nt = 0; nt < 4; nt++) {
            mma16816(acc[nt], a[0], a[1], a[2], a[3], bh[nt][0], bh[nt][1]);
            mma16816(acc[nt], a[0], a[1], a[2], a[3], bl[nt][0], bl[nt][1]);
        }
    }
}

#define GEMM_PROLOG \
    extern __shared__ __align__(16) unsigned char smraw[]; \
    int tid = threadIdx.x; \
    int w = tid >> 5, lane = tid & 31; \
    int gid = lane >> 2, tig = lane & 3; \
    int rr = lane & 7, qq = lane >> 3; \
    int wm = w & 3, wn = w >> 2; \
    uint32_t smemU = (uint32_t)__cvta_generic_to_shared(smraw); \
    int aOff = (rr + (qq & 1) * 8) * 80 + ((qq >> 1) * 8) * 2; \
    int bOff = (rr + (qq >> 1) * 8) * 80 + ((qq & 1) * 8) * 2; \
    (void)gid; (void)tig; \
    float acc[4][4]; \
    _Pragma("unroll") for (int j = 0; j < 4; j++) \
    _Pragma("unroll") for (int t = 0; t < 4; t++) acc[j][t] = 0.f;

// ---------------- conv-as-GEMM: M=4096, K=4096, N=256 (single-B) ----------------
__global__ void __launch_bounds__(256) k_conv_mma(const float* __restrict__ x,
                                                  const float* __restrict__ srb) {
    GEMM_PROLOG
    int n0 = blockIdx.x * 64, m0 = blockIdx.y * 64;
    float2 rA[4]; __half rBh[8];
    conv_load_A(x, m0, 0, rA);
    gload_B1(g_wsrh, CC, 0, n0, rBh);
    gstore_A(rA, (__half*)smraw);
    gstore_B1(rBh, (__half*)(smraw + ABYTES));
    for (int k0 = 0; k0 < KCONV; k0 += 32) {
        int cur = (k0 >> 5) & 1;
        __syncthreads();
        bool more = (k0 + 32 < KCONV);
        if (more) {
            conv_load_A(x, m0, k0 + 32, rA);
            gload_B1(g_wsrh, CC, k0 + 32, n0, rBh);
        }
        uint32_t bu = smemU + cur * BUF1;
        mma_step1(bu, bu + ABYTES, acc, wm, wn, aOff, bOff);
        if (more) {
            gstore_A(rA, (__half*)(smraw + (cur ^ 1) * BUF1));
            gstore_B1(rBh, (__half*)(smraw + (cur ^ 1) * BUF1 + ABYTES));
        }
    }
    #pragma unroll
    for (int nt = 0; nt < 4; nt++) {
        int r0 = m0 + wm * 16 + gid;
        int cb = n0 + wn * 32 + nt * 8 + tig * 2;
        g_xr[(size_t)r0 * CC + cb]       = acc[nt][0] + srb[cb];
        g_xr[(size_t)r0 * CC + cb + 1]   = acc[nt][1] + srb[cb + 1];
        g_xr[(size_t)(r0+8) * CC + cb]   = acc[nt][2] + srb[cb];
        g_xr[(size_t)(r0+8) * CC + cb+1] = acc[nt][3] + srb[cb + 1];
    }
}

// ---------------- LayerNorm ----------------
__global__ void __launch_bounds__(256) k_layernorm(const float* __restrict__ gamma,
                                                   const float* __restrict__ beta) {
    int row  = blockIdx.x * 8 + (threadIdx.x >> 5);
    int lane = threadIdx.x & 31;
    float* xr = g_xr + (size_t)row * CC;
    float v[8], s = 0.f;
    #pragma unroll
    for (int i = 0; i < 8; i++) { v[i] = xr[lane + i * 32]; s += v[i]; }
    #pragma unroll
    for (int o = 16; o; o >>= 1) s += __shfl_xor_sync(0xffffffffu, s, o);
    float mu = s * (1.f / 256.f), s2 = 0.f;
    #pragma unroll
    for (int i = 0; i < 8; i++) { float d = v[i] - mu; s2 += d * d; }
    #pragma unroll
    for (int o = 16; o; o >>= 1) s2 += __shfl_xor_sync(0xffffffffu, s2, o);
    float rstd = rsqrtf(s2 * (1.f / 256.f) + 1e-5f);
    #pragma unroll
    for (int i = 0; i < 8; i++) {
        int c = lane + i * 32;
        xr[c] = (v[i] - mu) * rstd * gamma[c] + beta[c];
    }
}

// ---------------- KV projection: M=4096, K=256, N=512 (single-B) ----------------
__global__ void __launch_bounds__(256) k_kv_mma() {
    GEMM_PROLOG
    int n0 = blockIdx.x * 64, m0 = blockIdx.y * 64;
    float2 rA[4]; __half rBh[8];
    gload_A(g_xr, CC, m0, 0, rA);
    gload_B1(g_wkvh, 2 * CC, 0, n0, rBh);
    gstore_A(rA, (__half*)smraw);
    gstore_B1(rBh, (__half*)(smraw + ABYTES));
    for (int k0 = 0; k0 < CC; k0 += 32) {
        int cur = (k0 >> 5) & 1;
        __syncthreads();
        bool more = (k0 + 32 < CC);
        if (more) {
            gload_A(g_xr, CC, m0, k0 + 32, rA);
            gload_B1(g_wkvh, 2 * CC, k0 + 32, n0, rBh);
        }
        uint32_t bu = smemU + cur * BUF1;
        mma_step1(bu, bu + ABYTES, acc, wm, wn, aOff, bOff);
        if (more) {
            gstore_A(rA, (__half*)(smraw + (cur ^ 1) * BUF1));
            gstore_B1(rBh, (__half*)(smraw + (cur ^ 1) * BUF1 + ABYTES));
        }
    }
    #pragma unroll
    for (int nt = 0; nt < 4; nt++)
        #pragma unroll
        for (int e = 0; e < 4; e++) {
            int r = m0 + wm * 16 + gid + (e >= 2 ? 8 : 0);
            int n = n0 + wn * 32 + nt * 8 + tig * 2 + (e & 1);
            int b = r >> 10, pos = r & 1023;
            int half = n >> 8, hh = (n >> 5) & 7, d = n & 31;
            size_t dst = ((size_t)((b * NHH + hh) * NKV + pos)) * HDD + d;
            __half v = __float2half_rn(acc[nt][e]);
            if (half == 0) g_kh[dst] = v; else g_vh[dst] = v;
        }
}

// ---------------- Q projection: M=16384, K=256, N=256 (single-B) ----------------
__global__ void __launch_bounds__(256) k_qproj_mma(const float* __restrict__ q) {
    GEMM_PROLOG
    int n0 = blockIdx.x * 64, m0 = blockIdx.y * 64;
    float2 rA[4]; __half rBh[8];
    gload_A(q, CC, m0, 0, rA);
    gload_B1(g_wqh, CC, 0, n0, rBh);
    gstore_A(rA, (__half*)smraw);
    gstore_B1(rBh, (__half*)(smraw + ABYTES));
    for (int k0 = 0; k0 < CC; k0 += 32) {
        int cur = (k0 >> 5) & 1;
        __syncthreads();
        bool more = (k0 + 32 < CC);
        if (more) {
            gload_A(q, CC, m0, k0 + 32, rA);
            gload_B1(g_wqh, CC, k0 + 32, n0, rBh);
        }
        uint32_t bu = smemU + cur * BUF1;
        mma_step1(bu, bu + ABYTES, acc, wm, wn, aOff, bOff);
        if (more) {
            gstore_A(rA, (__half*)(smraw + (cur ^ 1) * BUF1));
            gstore_B1(rBh, (__half*)(smraw + (cur ^ 1) * BUF1 + ABYTES));
        }
    }
    #pragma unroll
    for (int nt = 0; nt < 4; nt++)
        #pragma unroll
        for (int e = 0; e < 4; e++) {
            int r = m0 + wm * 16 + gid + (e >= 2 ? 8 : 0);
            int n = n0 + wn * 32 + nt * 8 + tig * 2 + (e & 1);
            g_qhh[(size_t)r * CC + n] = __float2half_rn(acc[nt][e]);
        }
}

// ---------------- Output projection: M=16384, K=256, N=256 (split-B) ----------------
__global__ void __launch_bounds__(256) k_proj_mma(const float* __restrict__ bp,
                                                  float* __restrict__ out) {
    GEMM_PROLOG
    int n0 = blockIdx.x * 64, m0 = blockIdx.y * 64;
    float2 rA[4]; __half rBh[8], rBl[8];
    gload_A(g_o, CC, m0, 0, rA);
    gload_B2(g_pwh, g_pwl, CC, 0, n0, rBh, rBl);
    gstore_A(rA, (__half*)smraw);
    gstore_B2(rBh, rBl, (__half*)(smraw + ABYTES), (__half*)(smraw + ABYTES + BBYTES));
    for (int k0 = 0; k0 < CC; k0 += 32) {
        int cur = (k0 >> 5) & 1;
        __syncthreads();
        bool more = (k0 + 32 < CC);
        if (more) {
            gload_A(g_o, CC, m0, k0 + 32, rA);
            gload_B2(g_pwh, g_pwl, CC, k0 + 32, n0, rBh, rBl);
        }
        uint32_t bu = smemU + cur * BUF2;
        mma_step2(bu, bu + ABYTES, bu + ABYTES + BBYTES, acc, wm, wn, aOff, bOff);
        if (more) {
            gstore_A(rA, (__half*)(smraw + (cur ^ 1) * BUF2));
            gstore_B2(rBh, rBl, (__half*)(smraw + (cur ^ 1) * BUF2 + ABYTES),
                      (__half*)(smraw + (cur ^ 1) * BUF2 + ABYTES + BBYTES));
        }
    }
    #pragma unroll
    for (int nt = 0; nt < 4; nt++)
        #pragma unroll
        for (int e = 0; e < 4; e++) {
            int r = m0 + wm * 16 + gid + (e >= 2 ? 8 : 0);
            int n = n0 + wn * 32 + nt * 8 + tig * 2 + (e & 1);
            out[(size_t)r * CC + n] = acc[nt][e] + bp[n];
        }
}

// ---------------- Flash attention (R11 verbatim) ----------------
#define VT_S 130

__global__ void __launch_bounds__(256) k_attn_flash(const int* __restrict__ qlen) {
    __shared__ __half Ks[128 * 40];
    __shared__ __half Vt[32 * VT_S];

    int tid = threadIdx.x;
    int w = tid >> 5, lane = tid & 31;
    int gid = lane >> 2, tig = lane & 3;
    int h = blockIdx.y;
    int q0 = blockIdx.x * 128;

    int l0 = qlen[0], l1 = qlen[1], l2 = qlen[2];
    int b = 0;
    if (q0 >= l0) b = 1;
    if (q0 >= l0 + l1) b = 2;
    if (q0 >= l0 + l1 + l2) b = 3;

    const __half* Kb = g_kh + ((size_t)(b * NHH + h) * NKV) * HDD;
    const __half* Vb = g_vh + ((size_t)(b * NHH + h) * NKV) * HDD;

    uint32_t aQ[2][4];
    {
        const __half* Qp = g_qhh + (size_t)(q0 + w * 16) * CC + h * HDD;
        #pragma unroll
        for (int kc = 0; kc < 2; kc++) {
            int c = kc * 16 + tig * 2;
            aQ[kc][0] = *(const uint32_t*)(Qp + (size_t)gid * CC + c);
            aQ[kc][1] = *(const uint32_t*)(Qp + (size_t)(gid + 8) * CC + c);
            aQ[kc][2] = *(const uint32_t*)(Qp + (size_t)gid * CC + c + 8);
            aQ[kc][3] = *(const uint32_t*)(Qp + (size_t)(gid + 8) * CC + c + 8);
        }
    }

    float o[4][4];
    #pragma unroll
    for (int i = 0; i < 4; i++)
        #pragma unroll
        for (int j = 0; j < 4; j++) o[i][j] = 0.f;
    float mrow[2] = {-1e30f, -1e30f};
    float lsum[2] = {0.f, 0.f};

    for (int kt = 0; kt < 8; kt++) {
        #pragma unroll
        for (int i = 0; i < 8; i++) {
            int idx = tid + i * 256;
            int key = idx >> 4, dp = idx & 15;
            ((uint32_t*)Ks)[key * 20 + dp] =
                *(const uint32_t*)(Kb + (size_t)(kt * 128 + key) * HDD + dp * 2);
        }
        #pragma unroll
        for (int i = 0; i < 8; i++) {
            int idx = tid + i * 256;
            int key = idx >> 4, dp = idx & 15;
            uint32_t u = *(const uint32_t*)(Vb + (size_t)(kt * 128 + key) * HDD + dp * 2);
            __half2 h2 = *(__half2*)&u;
            Vt[(dp * 2) * VT_S + key]     = __low2half(h2);
            Vt[(dp * 2 + 1) * VT_S + key] = __high2half(h2);
        }
        __syncthreads();

        float c[16][4];
        #pragma unroll
        for (int t = 0; t < 16; t++) {
            c[t][0] = c[t][1] = c[t][2] = c[t][3] = 0.f;
            #pragma unroll
            for (int kc = 0; kc < 2; kc++) {
                int cc = kc * 16 + tig * 2;
                uint32_t b0 = *(const uint32_t*)(Ks + (t * 8 + gid) * 40 + cc);
                uint32_t b1 = *(const uint32_t*)(Ks + (t * 8 + gid) * 40 + cc + 8);
                mma16816(c[t], aQ[kc][0], aQ[kc][1], aQ[kc][2], aQ[kc][3], b0, b1);
            }
        }

        float tm0 = -1e30f, tm1 = -1e30f;
        #pragma unroll
        for (int t = 0; t < 16; t++) {
            tm0 = fmaxf(tm0, fmaxf(c[t][0], c[t][1]));
            tm1 = fmaxf(tm1, fmaxf(c[t][2], c[t][3]));
        }
        tm0 = fmaxf(tm0, __shfl_xor_sync(0xffffffffu, tm0, 1));
        tm0 = fmaxf(tm0, __shfl_xor_sync(0xffffffffu, tm0, 2));
        tm1 = fmaxf(tm1, __shfl_xor_sync(0xffffffffu, tm1, 1));
        tm1 = fmaxf(tm1, __shfl_xor_sync(0xffffffffu, tm1, 2));
        float mn0 = fmaxf(mrow[0], tm0);
        float mn1 = fmaxf(mrow[1], tm1);
        float f0 = exp2f((mrow[0] - mn0) * C2E);
        float f1 = exp2f((mrow[1] - mn1) * C2E);
        mrow[0] = mn0; mrow[1] = mn1;
        lsum[0] *= f0; lsum[1] *= f1;
        #pragma unroll
        for (int nt = 0; nt < 4; nt++) {
            o[nt][0] *= f0; o[nt][1] *= f0;
            o[nt][2] *= f1; o[nt][3] *= f1;
        }
        float ps0 = 0.f, ps1 = 0.f;
        uint32_t pf[16][2];
        #pragma unroll
        for (int t = 0; t < 16; t++) {
            float p0 = exp2f((c[t][0] - mn0) * C2E);
            float p1 = exp2f((c[t][1] - mn0) * C2E);
            float p2 = exp2f((c[t][2] - mn1) * C2E);
            float p3 = exp2f((c[t][3] - mn1) * C2E);
            ps0 += p0 + p1;
            ps1 += p2 + p3;
            pf[t][0] = pack2(__float2half_rn(p0), __float2half_rn(p1));
            pf[t][1] = pack2(__float2half_rn(p2), __float2half_rn(p3));
        }
        lsum[0] += ps0;
        lsum[1] += ps1;

        #pragma unroll
        for (int j = 0; j < 8; j++) {
            uint32_t a0 = pf[2 * j][0];
            uint32_t a1 = pf[2 * j][1];
            uint32_t a2 = pf[2 * j + 1][0];
            uint32_t a3 = pf[2 * j + 1][1];
            #pragma unroll
            for (int nt = 0; nt < 4; nt++) {
                int d = nt * 8 + gid;
                uint32_t b0 = *(const uint32_t*)(Vt + d * VT_S + 16 * j + tig * 2);
                uint32_t b1 = *(const uint32_t*)(Vt + d * VT_S + 16 * j + tig * 2 + 8);
                mma16816(o[nt], a0, a1, a2, a3, b0, b1);
            }
        }
        __syncthreads();
    }

    lsum[0] += __shfl_xor_sync(0xffffffffu, lsum[0], 1);
    lsum[0] += __shfl_xor_sync(0xffffffffu, lsum[0], 2);
    lsum[1] += __shfl_xor_sync(0xffffffffu, lsum[1], 1);
    lsum[1] += __shfl_xor_sync(0xffffffffu, lsum[1], 2);

    float i0 = 1.f / lsum[0], i1 = 1.f / lsum[1];
    float* Op = g_o + (size_t)(q0 + w * 16) * CC + h * HDD;
    #pragma unroll
    for (int nt = 0; nt < 4; nt++) {
        int col = nt * 8 + tig * 2;
        float2 v0 = make_float2(o[nt][0] * i0, o[nt][1] * i0);
        float2 v1 = make_float2(o[nt][2] * i1, o[nt][3] * i1);
        *(float2*)(Op + (size_t)gid * CC + col)       = v0;
        *(float2*)(Op + (size_t)(gid + 8) * CC + col) = v1;
    }
}

// ---------------- launch: two-stream fork-join (graph-capturable) ----------------
extern "C" void kernel_launch(void* const* d_in, const int* in_sizes, int n_in,
                              void* d_out, int out_size) {
    const float* x      = (const float*)d_in[0];
    const float* q      = (const float*)d_in[1];
    const int*   qlen   = (const int*)  d_in[4];
    const float* w_q    = (const float*)d_in[5];
    const float* w_kv   = (const float*)d_in[6];
    const float* sr_w   = (const float*)d_in[7];
    const float* sr_b   = (const float*)d_in[8];
    const float* ln_g   = (const float*)d_in[9];
    const float* ln_b   = (const float*)d_in[10];
    const float* proj_w = (const float*)d_in[11];
    const float* proj_b = (const float*)d_in[12];
    float* out = (float*)d_out;

    cudaFuncSetAttribute(k_conv_mma,  cudaFuncAttributeMaxDynamicSharedMemorySize, SMEM1);
    cudaFuncSetAttribute(k_kv_mma,    cudaFuncAttributeMaxDynamicSharedMemorySize, SMEM1);
    cudaFuncSetAttribute(k_qproj_mma, cudaFuncAttributeMaxDynamicSharedMemorySize, SMEM1);
    cudaFuncSetAttribute(k_proj_mma,  cudaFuncAttributeMaxDynamicSharedMemorySize, SMEM2);

    __half *wqh, *wkvh, *pwh, *pwl;
    cudaGetSymbolAddress((void**)&wqh,  g_wqh);
    cudaGetSymbolAddress((void**)&wkvh, g_wkvh);
    cudaGetSymbolAddress((void**)&pwh,  g_pwh);
    cudaGetSymbolAddress((void**)&pwl,  g_pwl);

    // side stream + events (created fresh each call; intentionally not destroyed
    // so the capture's fork/join edges stay valid — no device memory involved)
    cudaStream_t s2;
    cudaEvent_t eFork, eJoin;
    cudaStreamCreateWithFlags(&s2, cudaStreamNonBlocking);
    cudaEventCreateWithFlags(&eFork, cudaEventDisableTiming);
    cudaEventCreateWithFlags(&eJoin, cudaEventDisableTiming);

    // fork: s2 branches off the main (capture) stream
    cudaEventRecord(eFork, 0);
    cudaStreamWaitEvent(s2, eFork, 0);

    // --- side stream: q-projection path + proj_w split (independent of conv chain) ---
    k_cvt<<<(CC*CC + 255)/256, 256, 0, s2>>>(w_q, wqh, CC*CC);
    k_split<<<(CC*CC + 255)/256, 256, 0, s2>>>(proj_w, pwh, pwl, CC*CC);
    k_qproj_mma<<<dim3(CC/64, TQ/64), 256, SMEM1, s2>>>(q);
    cudaEventRecord(eJoin, s2);

    // --- main stream: conv -> LN -> kv chain ---
    k_cvt_srw<<<(KCONV*CC + 255)/256, 256>>>(sr_w);
    k_cvt<<<(CC*2*CC + 255)/256, 256>>>(w_kv, wkvh, CC*2*CC);
    k_conv_mma<<<dim3(CC/64, (BB*NKV)/64), 256, SMEM1>>>(x, sr_b);
    k_layernorm<<<(BB*NKV)/8, 256>>>(ln_g, ln_b);
    k_kv_mma<<<dim3((2*CC)/64, (BB*NKV)/64), 256, SMEM1>>>();

    // join: attention needs both kv (main) and qproj (s2)
    cudaStreamWaitEvent(0, eJoin, 0);

    k_attn_flash<<<dim3(TQ/128, NHH), 256>>>(qlen);
    k_proj_mma<<<dim3(CC/64, TQ/64), 256, SMEM2>>>(proj_b, out);
}

// round 15
// speedup vs baseline: 1.1344x; 1.0751x over previous
#include <cuda_runtime.h>
#include <cuda_fp16.h>
#include <math.h>
#include <stdint.h>

#define BB    4
#define NTOT  16384
#define CC    256
#define NHH   8
#define HDD   32
#define NKV   1024
#define KCONV 4096
#define TQ    16384
#define SCALE 0.17677669529663689f
#define C2E   0.25503486963f   // SCALE * log2(e)

// GEMM tiles: BM=64, BN=64, BK=32; smem row stride 40 halves (80 B)
#define ABYTES 5120
#define BBYTES 5120
#define BUF1   (ABYTES + BBYTES)        // 10240
#define SMEM1  (2*BUF1)
#define BUF2   (ABYTES + 2*BBYTES)      // 15360
#define SMEM2  (2*BUF2)

// ---------------- scratch (device globals) ----------------
__device__ __half g_wqh [CC*CC];
__device__ __half g_wkvh[CC*2*CC];
__device__ __half g_pwh [CC*CC],  g_pwl[CC*CC];
__device__ __half g_wsrh[KCONV*CC];
__device__ float  g_xr [BB*NKV*CC];
__device__ __half g_kh [BB*NHH*NKV*HDD], g_vh[BB*NHH*NKV*HDD];
__device__ __half g_qhh[TQ*CC];
__device__ float  g_o  [TQ*CC];

// ---------------- helpers ----------------
__device__ __forceinline__ void fsplit(float x, __half& h, __half& l) {
    h = __float2half_rn(x);
    l = __float2half_rn(x - __half2float(h));
}

__device__ __forceinline__ void mma16816(float* c,
    uint32_t a0, uint32_t a1, uint32_t a2, uint32_t a3, uint32_t b0, uint32_t b1) {
    asm volatile("mma.sync.aligned.m16n8k16.row.col.f32.f16.f16.f32 "
        "{%0,%1,%2,%3}, {%4,%5,%6,%7}, {%8,%9}, {%0,%1,%2,%3};\n"
        : "+f"(c[0]), "+f"(c[1]), "+f"(c[2]), "+f"(c[3])
        : "r"(a0), "r"(a1), "r"(a2), "r"(a3), "r"(b0), "r"(b1));
}

__device__ __forceinline__ void ldsm4(uint32_t& r0, uint32_t& r1, uint32_t& r2,
                                      uint32_t& r3, uint32_t addr) {
    asm volatile("ldmatrix.sync.aligned.m8n8.x4.shared.b16 {%0,%1,%2,%3}, [%4];"
        : "=r"(r0), "=r"(r1), "=r"(r2), "=r"(r3) : "r"(addr));
}

__device__ __forceinline__ uint32_t pack2(__half lo, __half hi) {
    __half2 t = __halves2half2(lo, hi);
    return *(uint32_t*)&t;
}

// ---------------- weight convert kernels ----------------
__global__ void k_cvt(const float* __restrict__ src, __half* __restrict__ dh, int n) {
    int i = blockIdx.x * 256 + threadIdx.x;
    if (i < n) dh[i] = __float2half_rn(src[i]);
}

__global__ void k_split(const float* __restrict__ src, __half* __restrict__ dh,
                        __half* __restrict__ dl, int n) {
    int i = blockIdx.x * 256 + threadIdx.x;
    if (i < n) { __half h, l; fsplit(src[i], h, l); dh[i] = h; dl[i] = l; }
}

// coalesced tiled transpose: srw [co=256][ci=256][p=16] -> g_wsrh [k=p*256+ci][co]
__global__ void __launch_bounds__(256) k_cvt_srw(const float* __restrict__ srw) {
    __shared__ float tile[32][33];
    int t0  = blockIdx.x * 32;     // 128 tiles across (ci*16+p) = 4096
    int co0 = blockIdx.y * 32;     // 8 tiles across co = 256
    int tid = threadIdx.x;
    #pragma unroll
    for (int i = 0; i < 4; i++) {
        int e = tid + i * 256;
        int co = e >> 5, t = e & 31;
        tile[co][t] = srw[(size_t)(co0 + co) * KCONV + t0 + t];    // coalesced in t
    }
    __syncthreads();
    #pragma unroll
    for (int i = 0; i < 4; i++) {
        int e = tid + i * 256;
        int t = e >> 5, co = e & 31;
        int tt = t0 + t;
        int ci = tt >> 4, p = tt & 15;
        int k = p * 256 + ci;
        g_wsrh[(size_t)k * CC + co0 + co] = __float2half_rn(tile[co][t]);  // coalesced in co
    }
}

// ---------------- loaders (BM=64, BN=64, BK=32; stride 40 halves) ----------------
__device__ __forceinline__ void gload_A(const float* __restrict__ A, int K,
                                        int m0, int k0, float2 rA[4]) {
    int tid = threadIdx.x;
    #pragma unroll
    for (int i = 0; i < 4; i++) {
        int l = tid + i * 256;
        int m = l >> 4, kp = l & 15;
        rA[i] = *(const float2*)(A + (size_t)(m0 + m) * K + k0 + kp * 2);
    }
}

__device__ __forceinline__ void gstore_A(const float2 rA[4], __half* Ash) {
    int tid = threadIdx.x;
    #pragma unroll
    for (int i = 0; i < 4; i++) {
        int l = tid + i * 256;
        int m = l >> 4, kp = l & 15;
        ((uint32_t*)Ash)[m * 20 + kp] =
            pack2(__float2half_rn(rA[i].x), __float2half_rn(rA[i].y));
    }
}

__device__ __forceinline__ void gload_B1(const __half* __restrict__ Bh,
                                         int N, int k0, int n0, __half rBh[8]) {
    int tid = threadIdx.x;
    #pragma unroll
    for (int i = 0; i < 8; i++) {
        int l = tid + i * 256;
        int kk = l >> 6, n = l & 63;
        rBh[i] = Bh[(size_t)(k0 + kk) * N + n0 + n];
    }
}

__device__ __forceinline__ void gstore_B1(const __half rBh[8], __half* Bsh) {
    int tid = threadIdx.x;
    #pragma unroll
    for (int i = 0; i < 8; i++) {
        int l = tid + i * 256;
        int kk = l >> 6, n = l & 63;
        Bsh[n * 40 + kk] = rBh[i];
    }
}

__device__ __forceinline__ void gload_B2(const __half* __restrict__ Bh,
                                         const __half* __restrict__ Bl,
                                         int N, int k0, int n0,
                                         __half rBh[8], __half rBl[8]) {
    int tid = threadIdx.x;
    #pragma unroll
    for (int i = 0; i < 8; i++) {
        int l = tid + i * 256;
        int kk = l >> 6, n = l & 63;
        size_t g = (size_t)(k0 + kk) * N + n0 + n;
        rBh[i] = Bh[g];
        rBl[i] = Bl[g];
    }
}

__device__ __forceinline__ void gstore_B2(const __half rBh[8], const __half rBl[8],
                                          __half* Bsh, __half* Bsl) {
    int tid = threadIdx.x;
    #pragma unroll
    for (int i = 0; i < 8; i++) {
        int l = tid + i * 256;
        int kk = l >> 6, n = l & 63;
        Bsh[n * 40 + kk] = rBh[i];
        Bsl[n * 40 + kk] = rBl[i];
    }
}

// conv A gather loader (x fp32, NCHW-gathered); BM=64
__device__ __forceinline__ void conv_load_A(const float* __restrict__ x,
                                            int m0, int k0, float2 rA[4]) {
    int tid = threadIdx.x;
    int p = k0 >> 8, cib = k0 & 255;
    int kh = p >> 2, kw = p & 3;
    #pragma unroll
    for (int i = 0; i < 4; i++) {
        int l = tid + i * 256;
        int m = l >> 4, kp = l & 15;
        int mm = m0 + m;
        int b = mm >> 10, rem = mm & 1023, oh = rem >> 5, ow = rem & 31;
        size_t g = ((size_t)(b * NTOT + (oh * 4 + kh) * 128 + ow * 4 + kw)) * CC + cib + kp * 2;
        rA[i] = *(const float2*)(x + g);
    }
}

// ---------------- mma steps (one BK=32), warp tile 16x32 ----------------
__device__ __forceinline__ void mma_step1(uint32_t aU, uint32_t bU,
                                          float acc[4][4], int wm, int wn,
                                          int aOff, int bOff) {
    #pragma unroll
    for (int kc = 0; kc < 2; kc++) {
        int cB = kc * 32;
        uint32_t a[4], bh[4][2];
        ldsm4(a[0], a[1], a[2], a[3], aU + (wm * 16) * 80 + cB + aOff);
        #pragma unroll
        for (int pp = 0; pp < 2; pp++) {
            uint32_t base = (wn * 32 + pp * 16) * 80 + cB;
            ldsm4(bh[2*pp][0], bh[2*pp][1], bh[2*pp+1][0], bh[2*pp+1][1], bU + base + bOff);
        }
        #pragma unroll
        for (int nt = 0; nt < 4; nt++)
            mma16816(acc[nt], a[0], a[1], a[2], a[3], bh[nt][0], bh[nt][1]);
    }
}

__device__ __forceinline__ void mma_step2(uint32_t aU, uint32_t bhU, uint32_t blU,
                                          float acc[4][4], int wm, int wn,
                                          int aOff, int bOff) {
    #pragma unroll
    for (int kc = 0; kc < 2; kc++) {
        int cB = kc * 32;
        uint32_t a[4], bh[4][2], bl[4][2];
        ldsm4(a[0], a[1], a[2], a[3], aU + (wm * 16) * 80 + cB + aOff);
        #pragma unroll
        for (int pp = 0; pp < 2; pp++) {
            uint32_t base = (wn * 32 + pp * 16) * 80 + cB;
            ldsm4(bh[2*pp][0], bh[2*pp][1], bh[2*pp+1][0], bh[2*pp+1][1], bhU + base + bOff);
            ldsm4(bl[2*pp][0], bl[2*pp][1], bl[2*pp+1][0], bl[2*pp+1][1], blU + base + bOff);
        }
        #pragma unroll
        for (int nt = 0; nt < 4; nt++) {
            mma16816(acc[nt], a[0], a[1], a[2], a[3], bh[nt][0], bh[nt][1]);
            mma16816(acc[nt], a[0], a[1], a[2], a[3], bl[nt][0], bl[nt][1]);
        }
    }
}

#define GEMM_PROLOG \
    extern __shared__ __align__(16) unsigned char smraw[]; \
    int tid = threadIdx.x; \
    int w = tid >> 5, lane = tid & 31; \
    int gid = lane >> 2, tig = lane & 3; \
    int rr = lane & 7, qq = lane >> 3; \
    int wm = w & 3, wn = w >> 2; \
    uint32_t smemU = (uint32_t)__cvta_generic_to_shared(smraw); \
    int aOff = (rr + (qq & 1) * 8) * 80 + ((qq >> 1) * 8) * 2; \
    int bOff = (rr + (qq >> 1) * 8) * 80 + ((qq & 1) * 8) * 2; \
    (void)gid; (void)tig; \
    float acc[4][4]; \
    _Pragma("unroll") for (int j = 0; j < 4; j++) \
    _Pragma("unroll") for (int t = 0; t < 4; t++) acc[j][t] = 0.f;

// ---------------- conv-as-GEMM: M=4096, K=4096, N=256 (single-B) ----------------
__global__ void __launch_bounds__(256, 3) k_conv_mma(const float* __restrict__ x,
                                                     const float* __restrict__ srb) {
    GEMM_PROLOG
    int n0 = blockIdx.x * 64, m0 = blockIdx.y * 64;
    float2 rA[4]; __half rBh[8];
    conv_load_A(x, m0, 0, rA);
    gload_B1(g_wsrh, CC, 0, n0, rBh);
    gstore_A(rA, (__half*)smraw);
    gstore_B1(rBh, (__half*)(smraw + ABYTES));
    for (int k0 = 0; k0 < KCONV; k0 += 32) {
        int cur = (k0 >> 5) & 1;
        __syncthreads();
        bool more = (k0 + 32 < KCONV);
        if (more) {
            conv_load_A(x, m0, k0 + 32, rA);
            gload_B1(g_wsrh, CC, k0 + 32, n0, rBh);
        }
        uint32_t bu = smemU + cur * BUF1;
        mma_step1(bu, bu + ABYTES, acc, wm, wn, aOff, bOff);
        if (more) {
            gstore_A(rA, (__half*)(smraw + (cur ^ 1) * BUF1));
            gstore_B1(rBh, (__half*)(smraw + (cur ^ 1) * BUF1 + ABYTES));
        }
    }
    #pragma unroll
    for (int nt = 0; nt < 4; nt++) {
        int r0 = m0 + wm * 16 + gid;
        int cb = n0 + wn * 32 + nt * 8 + tig * 2;
        g_xr[(size_t)r0 * CC + cb]       = acc[nt][0] + srb[cb];
        g_xr[(size_t)r0 * CC + cb + 1]   = acc[nt][1] + srb[cb + 1];
        g_xr[(size_t)(r0+8) * CC + cb]   = acc[nt][2] + srb[cb];
        g_xr[(size_t)(r0+8) * CC + cb+1] = acc[nt][3] + srb[cb + 1];
    }
}

// ---------------- LayerNorm ----------------
__global__ void __launch_bounds__(256) k_layernorm(const float* __restrict__ gamma,
                                                   const float* __restrict__ beta) {
    int row  = blockIdx.x * 8 + (threadIdx.x >> 5);
    int lane = threadIdx.x & 31;
    float* xr = g_xr + (size_t)row * CC;
    float v[8], s = 0.f;
    #pragma unroll
    for (int i = 0; i < 8; i++) { v[i] = xr[lane + i * 32]; s += v[i]; }
    #pragma unroll
    for (int o = 16; o; o >>= 1) s += __shfl_xor_sync(0xffffffffu, s, o);
    float mu = s * (1.f / 256.f), s2 = 0.f;
    #pragma unroll
    for (int i = 0; i < 8; i++) { float d = v[i] - mu; s2 += d * d; }
    #pragma unroll
    for (int o = 16; o; o >>= 1) s2 += __shfl_xor_sync(0xffffffffu, s2, o);
    float rstd = rsqrtf(s2 * (1.f / 256.f) + 1e-5f);
    #pragma unroll
    for (int i = 0; i < 8; i++) {
        int c = lane + i * 32;
        xr[c] = (v[i] - mu) * rstd * gamma[c] + beta[c];
    }
}

// ---------------- KV projection: M=4096, K=256, N=512 (single-B) ----------------
__global__ void __launch_bounds__(256, 3) k_kv_mma() {
    GEMM_PROLOG
    int n0 = blockIdx.x * 64, m0 = blockIdx.y * 64;
    float2 rA[4]; __half rBh[8];
    gload_A(g_xr, CC, m0, 0, rA);
    gload_B1(g_wkvh, 2 * CC, 0, n0, rBh);
    gstore_A(rA, (__half*)smraw);
    gstore_B1(rBh, (__half*)(smraw + ABYTES));
    for (int k0 = 0; k0 < CC; k0 += 32) {
        int cur = (k0 >> 5) & 1;
        __syncthreads();
        bool more = (k0 + 32 < CC);
        if (more) {
            gload_A(g_xr, CC, m0, k0 + 32, rA);
            gload_B1(g_wkvh, 2 * CC, k0 + 32, n0, rBh);
        }
        uint32_t bu = smemU + cur * BUF1;
        mma_step1(bu, bu + ABYTES, acc, wm, wn, aOff, bOff);
        if (more) {
            gstore_A(rA, (__half*)(smraw + (cur ^ 1) * BUF1));
            gstore_B1(rBh, (__half*)(smraw + (cur ^ 1) * BUF1 + ABYTES));
        }
    }
    #pragma unroll
    for (int nt = 0; nt < 4; nt++)
        #pragma unroll
        for (int e = 0; e < 4; e++) {
            int r = m0 + wm * 16 + gid + (e >= 2 ? 8 : 0);
            int n = n0 + wn * 32 + nt * 8 + tig * 2 + (e & 1);
            int b = r >> 10, pos = r & 1023;
            int half = n >> 8, hh = (n >> 5) & 7, d = n & 31;
            size_t dst = ((size_t)((b * NHH + hh) * NKV + pos)) * HDD + d;
            __half v = __float2half_rn(acc[nt][e]);
            if (half == 0) g_kh[dst] = v; else g_vh[dst] = v;
        }
}

// ---------------- Q projection: M=16384, K=256, N=256 (single-B) ----------------
__global__ void __launch_bounds__(256, 3) k_qproj_mma(const float* __restrict__ q) {
    GEMM_PROLOG
    int n0 = blockIdx.x * 64, m0 = blockIdx.y * 64;
    float2 rA[4]; __half rBh[8];
    gload_A(q, CC, m0, 0, rA);
    gload_B1(g_wqh, CC, 0, n0, rBh);
    gstore_A(rA, (__half*)smraw);
    gstore_B1(rBh, (__half*)(smraw + ABYTES));
    for (int k0 = 0; k0 < CC; k0 += 32) {
        int cur = (k0 >> 5) & 1;
        __syncthreads();
        bool more = (k0 + 32 < CC);
        if (more) {
            gload_A(q, CC, m0, k0 + 32, rA);
            gload_B1(g_wqh, CC, k0 + 32, n0, rBh);
        }
        uint32_t bu = smemU + cur * BUF1;
        mma_step1(bu, bu + ABYTES, acc, wm, wn, aOff, bOff);
        if (more) {
            gstore_A(rA, (__half*)(smraw + (cur ^ 1) * BUF1));
            gstore_B1(rBh, (__half*)(smraw + (cur ^ 1) * BUF1 + ABYTES));
        }
    }
    #pragma unroll
    for (int nt = 0; nt < 4; nt++)
        #pragma unroll
        for (int e = 0; e < 4; e++) {
            int r = m0 + wm * 16 + gid + (e >= 2 ? 8 : 0);
            int n = n0 + wn * 32 + nt * 8 + tig * 2 + (e & 1);
            g_qhh[(size_t)r * CC + n] = __float2half_rn(acc[nt][e]);
        }
}

// ---------------- Output projection: M=16384, K=256, N=256 (split-B) ----------------
__global__ void __launch_bounds__(256) k_proj_mma(const float* __restrict__ bp,
                                                  float* __restrict__ out) {
    GEMM_PROLOG
    int n0 = blockIdx.x * 64, m0 = blockIdx.y * 64;
    float2 rA[4]; __half rBh[8], rBl[8];
    gload_A(g_o, CC, m0, 0, rA);
    gload_B2(g_pwh, g_pwl, CC, 0, n0, rBh, rBl);
    gstore_A(rA, (__half*)smraw);
    gstore_B2(rBh, rBl, (__half*)(smraw + ABYTES), (__half*)(smraw + ABYTES + BBYTES));
    for (int k0 = 0; k0 < CC; k0 += 32) {
        int cur = (k0 >> 5) & 1;
        __syncthreads();
        bool more = (k0 + 32 < CC);
        if (more) {
            gload_A(g_o, CC, m0, k0 + 32, rA);
            gload_B2(g_pwh, g_pwl, CC, k0 + 32, n0, rBh, rBl);
        }
        uint32_t bu = smemU + cur * BUF2;
        mma_step2(bu, bu + ABYTES, bu + ABYTES + BBYTES, acc, wm, wn, aOff, bOff);
        if (more) {
            gstore_A(rA, (__half*)(smraw + (cur ^ 1) * BUF2));
            gstore_B2(rBh, rBl, (__half*)(smraw + (cur ^ 1) * BUF2 + ABYTES),
                      (__half*)(smraw + (cur ^ 1) * BUF2 + ABYTES + BBYTES));
        }
    }
    #pragma unroll
    for (int nt = 0; nt < 4; nt++)
        #pragma unroll
        for (int e = 0; e < 4; e++) {
            int r = m0 + wm * 16 + gid + (e >= 2 ? 8 : 0);
            int n = n0 + wn * 32 + nt * 8 + tig * 2 + (e & 1);
            out[(size_t)r * CC + n] = acc[nt][e] + bp[n];
        }
}

// ---------------- Flash attention (R11 verbatim) ----------------
#define VT_S 130

__global__ void __launch_bounds__(256) k_attn_flash(const int* __restrict__ qlen) {
    __shared__ __half Ks[128 * 40];
    __shared__ __half Vt[32 * VT_S];

    int tid = threadIdx.x;
    int w = tid >> 5, lane = tid & 31;
    int gid = lane >> 2, tig = lane & 3;
    int h = blockIdx.y;
    int q0 = blockIdx.x * 128;

    int l0 = qlen[0], l1 = qlen[1], l2 = qlen[2];
    int b = 0;
    if (q0 >= l0) b = 1;
    if (q0 >= l0 + l1) b = 2;
    if (q0 >= l0 + l1 + l2) b = 3;

    const __half* Kb = g_kh + ((size_t)(b * NHH + h) * NKV) * HDD;
    const __half* Vb = g_vh + ((size_t)(b * NHH + h) * NKV) * HDD;

    uint32_t aQ[2][4];
    {
        const __half* Qp = g_qhh + (size_t)(q0 + w * 16) * CC + h * HDD;
        #pragma unroll
        for (int kc = 0; kc < 2; kc++) {
            int c = kc * 16 + tig * 2;
            aQ[kc][0] = *(const uint32_t*)(Qp + (size_t)gid * CC + c);
            aQ[kc][1] = *(const uint32_t*)(Qp + (size_t)(gid + 8) * CC + c);
            aQ[kc][2] = *(const uint32_t*)(Qp + (size_t)gid * CC + c + 8);
            aQ[kc][3] = *(const uint32_t*)(Qp + (size_t)(gid + 8) * CC + c + 8);
        }
    }

    float o[4][4];
    #pragma unroll
    for (int i = 0; i < 4; i++)
        #pragma unroll
        for (int j = 0; j < 4; j++) o[i][j] = 0.f;
    float mrow[2] = {-1e30f, -1e30f};
    float lsum[2] = {0.f, 0.f};

    for (int kt = 0; kt < 8; kt++) {
        #pragma unroll
        for (int i = 0; i < 8; i++) {
            int idx = tid + i * 256;
            int key = idx >> 4, dp = idx & 15;
            ((uint32_t*)Ks)[key * 20 + dp] =
                *(const uint32_t*)(Kb + (size_t)(kt * 128 + key) * HDD + dp * 2);
        }
        #pragma unroll
        for (int i = 0; i < 8; i++) {
            int idx = tid + i * 256;
            int key = idx >> 4, dp = idx & 15;
            uint32_t u = *(const uint32_t*)(Vb + (size_t)(kt * 128 + key) * HDD + dp * 2);
            __half2 h2 = *(__half2*)&u;
            Vt[(dp * 2) * VT_S + key]     = __low2half(h2);
            Vt[(dp * 2 + 1) * VT_S + key] = __high2half(h2);
        }
        __syncthreads();

        float c[16][4];
        #pragma unroll
        for (int t = 0; t < 16; t++) {
            c[t][0] = c[t][1] = c[t][2] = c[t][3] = 0.f;
            #pragma unroll
            for (int kc = 0; kc < 2; kc++) {
                int cc = kc * 16 + tig * 2;
                uint32_t b0 = *(const uint32_t*)(Ks + (t * 8 + gid) * 40 + cc);
                uint32_t b1 = *(const uint32_t*)(Ks + (t * 8 + gid) * 40 + cc + 8);
                mma16816(c[t], aQ[kc][0], aQ[kc][1], aQ[kc][2], aQ[kc][3], b0, b1);
            }
        }

        float tm0 = -1e30f, tm1 = -1e30f;
        #pragma unroll
        for (int t = 0; t < 16; t++) {
            tm0 = fmaxf(tm0, fmaxf(c[t][0], c[t][1]));
            tm1 = fmaxf(tm1, fmaxf(c[t][2], c[t][3]));
        }
        tm0 = fmaxf(tm0, __shfl_xor_sync(0xffffffffu, tm0, 1));
        tm0 = fmaxf(tm0, __shfl_xor_sync(0xffffffffu, tm0, 2));
        tm1 = fmaxf(tm1, __shfl_xor_sync(0xffffffffu, tm1, 1));
        tm1 = fmaxf(tm1, __shfl_xor_sync(0xffffffffu, tm1, 2));
        float mn0 = fmaxf(mrow[0], tm0);
        float mn1 = fmaxf(mrow[1], tm1);
        float f0 = exp2f((mrow[0] - mn0) * C2E);
        float f1 = exp2f((mrow[1] - mn1) * C2E);
        mrow[0] = mn0; mrow[1] = mn1;
        lsum[0] *= f0; lsum[1] *= f1;
        #pragma unroll
        for (int nt = 0; nt < 4; nt++) {
            o[nt][0] *= f0; o[nt][1] *= f0;
            o[nt][2] *= f1; o[nt][3] *= f1;
        }
        float ps0 = 0.f, ps1 = 0.f;
        uint32_t pf[16][2];
        #pragma unroll
        for (int t = 0; t < 16; t++) {
            float p0 = exp2f((c[t][0] - mn0) * C2E);
            float p1 = exp2f((c[t][1] - mn0) * C2E);
            float p2 = exp2f((c[t][2] - mn1) * C2E);
            float p3 = exp2f((c[t][3] - mn1) * C2E);
            ps0 += p0 + p1;
            ps1 += p2 + p3;
            pf[t][0] = pack2(__float2half_rn(p0), __float2half_rn(p1));
            pf[t][1] = pack2(__float2half_rn(p2), __float2half_rn(p3));
        }
        lsum[0] += ps0;
        lsum[1] += ps1;

        #pragma unroll
        for (int j = 0; j < 8; j++) {
            uint32_t a0 = pf[2 * j][0];
            uint32_t a1 = pf[2 * j][1];
            uint32_t a2 = pf[2 * j + 1][0];
            uint32_t a3 = pf[2 * j + 1][1];
            #pragma unroll
            for (int nt = 0; nt < 4; nt++) {
                int d = nt * 8 + gid;
                uint32_t b0 = *(const uint32_t*)(Vt + d * VT_S + 16 * j + tig * 2);
                uint32_t b1 = *(const uint32_t*)(Vt + d * VT_S + 16 * j + tig * 2 + 8);
                mma16816(o[nt], a0, a1, a2, a3, b0, b1);
            }
        }
        __syncthreads();
    }

    lsum[0] += __shfl_xor_sync(0xffffffffu, lsum[0], 1);
    lsum[0] += __shfl_xor_sync(0xffffffffu, lsum[0], 2);
    lsum[1] += __shfl_xor_sync(0xffffffffu, lsum[1], 1);
    lsum[1] += __shfl_xor_sync(0xffffffffu, lsum[1], 2);

    float i0 = 1.f / lsum[0], i1 = 1.f / lsum[1];
    float* Op = g_o + (size_t)(q0 + w * 16) * CC + h * HDD;
    #pragma unroll
    for (int nt = 0; nt < 4; nt++) {
        int col = nt * 8 + tig * 2;
        float2 v0 = make_float2(o[nt][0] * i0, o[nt][1] * i0);
        float2 v1 = make_float2(o[nt][2] * i1, o[nt][3] * i1);
        *(float2*)(Op + (size_t)gid * CC + col)       = v0;
        *(float2*)(Op + (size_t)(gid + 8) * CC + col) = v1;
    }
}

// ---------------- launch (serial, R11 order) ----------------
extern "C" void kernel_launch(void* const* d_in, const int* in_sizes, int n_in,
                              void* d_out, int out_size) {
    const float* x      = (const float*)d_in[0];
    const float* q      = (const float*)d_in[1];
    const int*   qlen   = (const int*)  d_in[4];
    const float* w_q    = (const float*)d_in[5];
    const float* w_kv   = (const float*)d_in[6];
    const float* sr_w   = (const float*)d_in[7];
    const float* sr_b   = (const float*)d_in[8];
    const float* ln_g   = (const float*)d_in[9];
    const float* ln_b   = (const float*)d_in[10];
    const float* proj_w = (const float*)d_in[11];
    const float* proj_b = (const float*)d_in[12];
    float* out = (float*)d_out;

    cudaFuncSetAttribute(k_conv_mma,  cudaFuncAttributeMaxDynamicSharedMemorySize, SMEM1);
    cudaFuncSetAttribute(k_kv_mma,    cudaFuncAttributeMaxDynamicSharedMemorySize, SMEM1);
    cudaFuncSetAttribute(k_qproj_mma, cudaFuncAttributeMaxDynamicSharedMemorySize, SMEM1);
    cudaFuncSetAttribute(k_proj_mma,  cudaFuncAttributeMaxDynamicSharedMemorySize, SMEM2);

    __half *wqh, *wkvh, *pwh, *pwl;
    cudaGetSymbolAddress((void**)&wqh,  g_wqh);
    cudaGetSymbolAddress((void**)&wkvh, g_wkvh);
    cudaGetSymbolAddress((void**)&pwh,  g_pwh);
    cudaGetSymbolAddress((void**)&pwl,  g_pwl);

    k_cvt<<<(CC*CC + 255)/256, 256>>>(w_q, wqh, CC*CC);
    k_cvt<<<(CC*2*CC + 255)/256, 256>>>(w_kv, wkvh, CC*2*CC);
    k_split<<<(CC*CC + 255)/256, 256>>>(proj_w, pwh, pwl, CC*CC);
    k_cvt_srw<<<dim3(KCONV/32, CC/32), 256>>>(sr_w);

    k_conv_mma<<<dim3(CC/64, (BB*NKV)/64), 256, SMEM1>>>(x, sr_b);
    k_layernorm<<<(BB*NKV)/8, 256>>>(ln_g, ln_b);
    k_kv_mma<<<dim3((2*CC)/64, (BB*NKV)/64), 256, SMEM1>>>();
    k_qproj_mma<<<dim3(CC/64, TQ/64), 256, SMEM1>>>(q);
    k_attn_flash<<<dim3(TQ/128, NHH), 256>>>(qlen);
    k_proj_mma<<<dim3(CC/64, TQ/64), 256, SMEM2>>>(proj_b, out);
}

// round 16
// speedup vs baseline: 1.1615x; 1.0239x over previous
#include <cuda_runtime.h>
#include <cuda_fp16.h>
#include <math.h>
#include <stdint.h>

#define BB    4
#define NTOT  16384
#define CC    256
#define NHH   8
#define HDD   32
#define NKV   1024
#define KCONV 4096
#define TQ    16384
#define SCALE 0.17677669529663689f
#define C2E   0.25503486963f   // SCALE * log2(e)

// BK=64 GEMM tiles (conv/kv/qproj): BM=64, BN=64, BK=64; row stride 72 halves (144 B)
#define A64B  9216              // 64*72 halves
#define B64B  9216
#define BUFX  (A64B + B64B)     // 18432
#define SMEMX (2*BUFX)          // 36864

// BK=32 split-B tile (proj): row stride 40 halves (80 B)
#define ABYTES 5120
#define BBYTES 5120
#define BUF2   (ABYTES + 2*BBYTES)      // 15360
#define SMEM2  (2*BUF2)

// ---------------- scratch (device globals) ----------------
__device__ __half g_wqh [CC*CC];
__device__ __half g_wkvh[CC*2*CC];
__device__ __half g_pwh [CC*CC],  g_pwl[CC*CC];
__device__ __half g_wsrh[KCONV*CC];
__device__ float  g_xr [BB*NKV*CC];
__device__ __half g_kh [BB*NHH*NKV*HDD], g_vh[BB*NHH*NKV*HDD];
__device__ __half g_qhh[TQ*CC];
__device__ float  g_o  [TQ*CC];

// ---------------- helpers ----------------
__device__ __forceinline__ void fsplit(float x, __half& h, __half& l) {
    h = __float2half_rn(x);
    l = __float2half_rn(x - __half2float(h));
}

__device__ __forceinline__ void mma16816(float* c,
    uint32_t a0, uint32_t a1, uint32_t a2, uint32_t a3, uint32_t b0, uint32_t b1) {
    asm volatile("mma.sync.aligned.m16n8k16.row.col.f32.f16.f16.f32 "
        "{%0,%1,%2,%3}, {%4,%5,%6,%7}, {%8,%9}, {%0,%1,%2,%3};\n"
        : "+f"(c[0]), "+f"(c[1]), "+f"(c[2]), "+f"(c[3])
        : "r"(a0), "r"(a1), "r"(a2), "r"(a3), "r"(b0), "r"(b1));
}

__device__ __forceinline__ void ldsm4(uint32_t& r0, uint32_t& r1, uint32_t& r2,
                                      uint32_t& r3, uint32_t addr) {
    asm volatile("ldmatrix.sync.aligned.m8n8.x4.shared.b16 {%0,%1,%2,%3}, [%4];"
        : "=r"(r0), "=r"(r1), "=r"(r2), "=r"(r3) : "r"(addr));
}

__device__ __forceinline__ uint32_t pack2(__half lo, __half hi) {
    __half2 t = __halves2half2(lo, hi);
    return *(uint32_t*)&t;
}

// ---------------- weight convert kernels ----------------
__global__ void k_cvt(const float* __restrict__ src, __half* __restrict__ dh, int n) {
    int i = blockIdx.x * 256 + threadIdx.x;
    if (i < n) dh[i] = __float2half_rn(src[i]);
}

__global__ void k_split(const float* __restrict__ src, __half* __restrict__ dh,
                        __half* __restrict__ dl, int n) {
    int i = blockIdx.x * 256 + threadIdx.x;
    if (i < n) { __half h, l; fsplit(src[i], h, l); dh[i] = h; dl[i] = l; }
}

// coalesced tiled transpose: srw [co][ci][p] -> g_wsrh [k=p*256+ci][co]
__global__ void __launch_bounds__(256) k_cvt_srw(const float* __restrict__ srw) {
    __shared__ float tile[32][33];
    int t0  = blockIdx.x * 32;
    int co0 = blockIdx.y * 32;
    int tid = threadIdx.x;
    #pragma unroll
    for (int i = 0; i < 4; i++) {
        int e = tid + i * 256;
        int co = e >> 5, t = e & 31;
        tile[co][t] = srw[(size_t)(co0 + co) * KCONV + t0 + t];
    }
    __syncthreads();
    #pragma unroll
    for (int i = 0; i < 4; i++) {
        int e = tid + i * 256;
        int t = e >> 5, co = e & 31;
        int tt = t0 + t;
        int ci = tt >> 4, p = tt & 15;
        int k = p * 256 + ci;
        g_wsrh[(size_t)k * CC + co0 + co] = __float2half_rn(tile[co][t]);
    }
}

// ---------------- BK=64 loaders (stride 72 halves) ----------------
__device__ __forceinline__ void gload_A64(const float* __restrict__ A, int K,
                                          int m0, int k0, float2 rA[8]) {
    int tid = threadIdx.x;
    #pragma unroll
    for (int i = 0; i < 8; i++) {
        int l = tid + i * 256;
        int m = l >> 5, kp = l & 31;
        rA[i] = *(const float2*)(A + (size_t)(m0 + m) * K + k0 + kp * 2);
    }
}

__device__ __forceinline__ void gstore_A64(const float2 rA[8], __half* Ash) {
    int tid = threadIdx.x;
    #pragma unroll
    for (int i = 0; i < 8; i++) {
        int l = tid + i * 256;
        int m = l >> 5, kp = l & 31;
        ((uint32_t*)Ash)[m * 36 + kp] =
            pack2(__float2half_rn(rA[i].x), __float2half_rn(rA[i].y));
    }
}

__device__ __forceinline__ void gload_B64(const __half* __restrict__ Bh,
                                          int N, int k0, int n0, __half rBh[16]) {
    int tid = threadIdx.x;
    #pragma unroll
    for (int i = 0; i < 16; i++) {
        int l = tid + i * 256;
        int kk = l >> 6, n = l & 63;
        rBh[i] = Bh[(size_t)(k0 + kk) * N + n0 + n];
    }
}

__device__ __forceinline__ void gstore_B64(const __half rBh[16], __half* Bsh) {
    int tid = threadIdx.x;
    #pragma unroll
    for (int i = 0; i < 16; i++) {
        int l = tid + i * 256;
        int kk = l >> 6, n = l & 63;
        Bsh[n * 72 + kk] = rBh[i];
    }
}

// conv A gather loader (x fp32, NCHW-gathered); BK=64 (p constant: 64 | 256)
__device__ __forceinline__ void conv_load_A64(const float* __restrict__ x,
                                              int m0, int k0, float2 rA[8]) {
    int tid = threadIdx.x;
    int p = k0 >> 8, cib = k0 & 255;
    int kh = p >> 2, kw = p & 3;
    #pragma unroll
    for (int i = 0; i < 8; i++) {
        int l = tid + i * 256;
        int m = l >> 5, kp = l & 31;
        int mm = m0 + m;
        int b = mm >> 10, rem = mm & 1023, oh = rem >> 5, ow = rem & 31;
        size_t g = ((size_t)(b * NTOT + (oh * 4 + kh) * 128 + ow * 4 + kw)) * CC + cib + kp * 2;
        rA[i] = *(const float2*)(x + g);
    }
}

// ---------------- BK=32 split-B loaders (proj only; stride 40 halves) ----------------
__device__ __forceinline__ void gload_A(const float* __restrict__ A, int K,
                                        int m0, int k0, float2 rA[4]) {
    int tid = threadIdx.x;
    #pragma unroll
    for (int i = 0; i < 4; i++) {
        int l = tid + i * 256;
        int m = l >> 4, kp = l & 15;
        rA[i] = *(const float2*)(A + (size_t)(m0 + m) * K + k0 + kp * 2);
    }
}

__device__ __forceinline__ void gstore_A(const float2 rA[4], __half* Ash) {
    int tid = threadIdx.x;
    #pragma unroll
    for (int i = 0; i < 4; i++) {
        int l = tid + i * 256;
        int m = l >> 4, kp = l & 15;
        ((uint32_t*)Ash)[m * 20 + kp] =
            pack2(__float2half_rn(rA[i].x), __float2half_rn(rA[i].y));
    }
}

__device__ __forceinline__ void gload_B2(const __half* __restrict__ Bh,
                                         const __half* __restrict__ Bl,
                                         int N, int k0, int n0,
                                         __half rBh[8], __half rBl[8]) {
    int tid = threadIdx.x;
    #pragma unroll
    for (int i = 0; i < 8; i++) {
        int l = tid + i * 256;
        int kk = l >> 6, n = l & 63;
        size_t g = (size_t)(k0 + kk) * N + n0 + n;
        rBh[i] = Bh[g];
        rBl[i] = Bl[g];
    }
}

__device__ __forceinline__ void gstore_B2(const __half rBh[8], const __half rBl[8],
                                          __half* Bsh, __half* Bsl) {
    int tid = threadIdx.x;
    #pragma unroll
    for (int i = 0; i < 8; i++) {
        int l = tid + i * 256;
        int kk = l >> 6, n = l & 63;
        Bsh[n * 40 + kk] = rBh[i];
        Bsl[n * 40 + kk] = rBl[i];
    }
}

// ---------------- mma steps ----------------
// BK=64 step, warp tile 16x32, stride 144 B
__device__ __forceinline__ void mma_step64(uint32_t aU, uint32_t bU,
                                           float acc[4][4], int wm, int wn,
                                           int aOff, int bOff) {
    #pragma unroll
    for (int kc = 0; kc < 4; kc++) {
        int cB = kc * 32;
        uint32_t a[4], bh[4][2];
        ldsm4(a[0], a[1], a[2], a[3], aU + (wm * 16) * 144 + cB + aOff);
        #pragma unroll
        for (int pp = 0; pp < 2; pp++) {
            uint32_t base = (wn * 32 + pp * 16) * 144 + cB;
            ldsm4(bh[2*pp][0], bh[2*pp][1], bh[2*pp+1][0], bh[2*pp+1][1], bU + base + bOff);
        }
        #pragma unroll
        for (int nt = 0; nt < 4; nt++)
            mma16816(acc[nt], a[0], a[1], a[2], a[3], bh[nt][0], bh[nt][1]);
    }
}

// BK=32 split-B step (proj), stride 80 B
__device__ __forceinline__ void mma_step2(uint32_t aU, uint32_t bhU, uint32_t blU,
                                          float acc[4][4], int wm, int wn,
                                          int aOff, int bOff) {
    #pragma unroll
    for (int kc = 0; kc < 2; kc++) {
        int cB = kc * 32;
        uint32_t a[4], bh[4][2], bl[4][2];
        ldsm4(a[0], a[1], a[2], a[3], aU + (wm * 16) * 80 + cB + aOff);
        #pragma unroll
        for (int pp = 0; pp < 2; pp++) {
            uint32_t base = (wn * 32 + pp * 16) * 80 + cB;
            ldsm4(bh[2*pp][0], bh[2*pp][1], bh[2*pp+1][0], bh[2*pp+1][1], bhU + base + bOff);
            ldsm4(bl[2*pp][0], bl[2*pp][1], bl[2*pp+1][0], bl[2*pp+1][1], blU + base + bOff);
        }
        #pragma unroll
        for (int nt = 0; nt < 4; nt++) {
            mma16816(acc[nt], a[0], a[1], a[2], a[3], bh[nt][0], bh[nt][1]);
            mma16816(acc[nt], a[0], a[1], a[2], a[3], bl[nt][0], bl[nt][1]);
        }
    }
}

#define GEMM_PROLOG64 \
    extern __shared__ __align__(16) unsigned char smraw[]; \
    int tid = threadIdx.x; \
    int w = tid >> 5, lane = tid & 31; \
    int gid = lane >> 2, tig = lane & 3; \
    int rr = lane & 7, qq = lane >> 3; \
    int wm = w & 3, wn = w >> 2; \
    uint32_t smemU = (uint32_t)__cvta_generic_to_shared(smraw); \
    int aOff = (rr + (qq & 1) * 8) * 144 + ((qq >> 1) * 8) * 2; \
    int bOff = (rr + (qq >> 1) * 8) * 144 + ((qq & 1) * 8) * 2; \
    (void)gid; (void)tig; \
    float acc[4][4]; \
    _Pragma("unroll") for (int j = 0; j < 4; j++) \
    _Pragma("unroll") for (int t = 0; t < 4; t++) acc[j][t] = 0.f;

#define GEMM_PROLOG32 \
    extern __shared__ __align__(16) unsigned char smraw[]; \
    int tid = threadIdx.x; \
    int w = tid >> 5, lane = tid & 31; \
    int gid = lane >> 2, tig = lane & 3; \
    int rr = lane & 7, qq = lane >> 3; \
    int wm = w & 3, wn = w >> 2; \
    uint32_t smemU = (uint32_t)__cvta_generic_to_shared(smraw); \
    int aOff = (rr + (qq & 1) * 8) * 80 + ((qq >> 1) * 8) * 2; \
    int bOff = (rr + (qq >> 1) * 8) * 80 + ((qq & 1) * 8) * 2; \
    (void)gid; (void)tig; \
    float acc[4][4]; \
    _Pragma("unroll") for (int j = 0; j < 4; j++) \
    _Pragma("unroll") for (int t = 0; t < 4; t++) acc[j][t] = 0.f;

// ---------------- conv-as-GEMM: M=4096, K=4096, N=256 (BK=64) ----------------
__global__ void __launch_bounds__(256, 3) k_conv_mma(const float* __restrict__ x,
                                                     const float* __restrict__ srb) {
    GEMM_PROLOG64
    int n0 = blockIdx.x * 64, m0 = blockIdx.y * 64;
    float2 rA[8]; __half rBh[16];
    conv_load_A64(x, m0, 0, rA);
    gload_B64(g_wsrh, CC, 0, n0, rBh);
    gstore_A64(rA, (__half*)smraw);
    gstore_B64(rBh, (__half*)(smraw + A64B));
    for (int k0 = 0; k0 < KCONV; k0 += 64) {
        int cur = (k0 >> 6) & 1;
        __syncthreads();
        bool more = (k0 + 64 < KCONV);
        if (more) {
            conv_load_A64(x, m0, k0 + 64, rA);
            gload_B64(g_wsrh, CC, k0 + 64, n0, rBh);
        }
        uint32_t bu = smemU + cur * BUFX;
        mma_step64(bu, bu + A64B, acc, wm, wn, aOff, bOff);
        if (more) {
            gstore_A64(rA, (__half*)(smraw + (cur ^ 1) * BUFX));
            gstore_B64(rBh, (__half*)(smraw + (cur ^ 1) * BUFX + A64B));
        }
    }
    #pragma unroll
    for (int nt = 0; nt < 4; nt++) {
        int r0 = m0 + wm * 16 + gid;
        int cb = n0 + wn * 32 + nt * 8 + tig * 2;
        g_xr[(size_t)r0 * CC + cb]       = acc[nt][0] + srb[cb];
        g_xr[(size_t)r0 * CC + cb + 1]   = acc[nt][1] + srb[cb + 1];
        g_xr[(size_t)(r0+8) * CC + cb]   = acc[nt][2] + srb[cb];
        g_xr[(size_t)(r0+8) * CC + cb+1] = acc[nt][3] + srb[cb + 1];
    }
}

// ---------------- LayerNorm ----------------
__global__ void __launch_bounds__(256) k_layernorm(const float* __restrict__ gamma,
                                                   const float* __restrict__ beta) {
    int row  = blockIdx.x * 8 + (threadIdx.x >> 5);
    int lane = threadIdx.x & 31;
    float* xr = g_xr + (size_t)row * CC;
    float v[8], s = 0.f;
    #pragma unroll
    for (int i = 0; i < 8; i++) { v[i] = xr[lane + i * 32]; s += v[i]; }
    #pragma unroll
    for (int o = 16; o; o >>= 1) s += __shfl_xor_sync(0xffffffffu, s, o);
    float mu = s * (1.f / 256.f), s2 = 0.f;
    #pragma unroll
    for (int i = 0; i < 8; i++) { float d = v[i] - mu; s2 += d * d; }
    #pragma unroll
    for (int o = 16; o; o >>= 1) s2 += __shfl_xor_sync(0xffffffffu, s2, o);
    float rstd = rsqrtf(s2 * (1.f / 256.f) + 1e-5f);
    #pragma unroll
    for (int i = 0; i < 8; i++) {
        int c = lane + i * 32;
        xr[c] = (v[i] - mu) * rstd * gamma[c] + beta[c];
    }
}

// ---------------- KV projection: M=4096, K=256, N=512 (BK=64) ----------------
__global__ void __launch_bounds__(256, 3) k_kv_mma() {
    GEMM_PROLOG64
    int n0 = blockIdx.x * 64, m0 = blockIdx.y * 64;
    float2 rA[8]; __half rBh[16];
    gload_A64(g_xr, CC, m0, 0, rA);
    gload_B64(g_wkvh, 2 * CC, 0, n0, rBh);
    gstore_A64(rA, (__half*)smraw);
    gstore_B64(rBh, (__half*)(smraw + A64B));
    for (int k0 = 0; k0 < CC; k0 += 64) {
        int cur = (k0 >> 6) & 1;
        __syncthreads();
        bool more = (k0 + 64 < CC);
        if (more) {
            gload_A64(g_xr, CC, m0, k0 + 64, rA);
            gload_B64(g_wkvh, 2 * CC, k0 + 64, n0, rBh);
        }
        uint32_t bu = smemU + cur * BUFX;
        mma_step64(bu, bu + A64B, acc, wm, wn, aOff, bOff);
        if (more) {
            gstore_A64(rA, (__half*)(smraw + (cur ^ 1) * BUFX));
            gstore_B64(rBh, (__half*)(smraw + (cur ^ 1) * BUFX + A64B));
        }
    }
    #pragma unroll
    for (int nt = 0; nt < 4; nt++)
        #pragma unroll
        for (int e = 0; e < 4; e++) {
            int r = m0 + wm * 16 + gid + (e >= 2 ? 8 : 0);
            int n = n0 + wn * 32 + nt * 8 + tig * 2 + (e & 1);
            int b = r >> 10, pos = r & 1023;
            int half = n >> 8, hh = (n >> 5) & 7, d = n & 31;
            size_t dst = ((size_t)((b * NHH + hh) * NKV + pos)) * HDD + d;
            __half v = __float2half_rn(acc[nt][e]);
            if (half == 0) g_kh[dst] = v; else g_vh[dst] = v;
        }
}

// ---------------- Q projection: M=16384, K=256, N=256 (BK=64) ----------------
__global__ void __launch_bounds__(256, 3) k_qproj_mma(const float* __restrict__ q) {
    GEMM_PROLOG64
    int n0 = blockIdx.x * 64, m0 = blockIdx.y * 64;
    float2 rA[8]; __half rBh[16];
    gload_A64(q, CC, m0, 0, rA);
    gload_B64(g_wqh, CC, 0, n0, rBh);
    gstore_A64(rA, (__half*)smraw);
    gstore_B64(rBh, (__half*)(smraw + A64B));
    for (int k0 = 0; k0 < CC; k0 += 64) {
        int cur = (k0 >> 6) & 1;
        __syncthreads();
        bool more = (k0 + 64 < CC);
        if (more) {
            gload_A64(q, CC, m0, k0 + 64, rA);
            gload_B64(g_wqh, CC, k0 + 64, n0, rBh);
        }
        uint32_t bu = smemU + cur * BUFX;
        mma_step64(bu, bu + A64B, acc, wm, wn, aOff, bOff);
        if (more) {
            gstore_A64(rA, (__half*)(smraw + (cur ^ 1) * BUFX));
            gstore_B64(rBh, (__half*)(smraw + (cur ^ 1) * BUFX + A64B));
        }
    }
    #pragma unroll
    for (int nt = 0; nt < 4; nt++)
        #pragma unroll
        for (int e = 0; e < 4; e++) {
            int r = m0 + wm * 16 + gid + (e >= 2 ? 8 : 0);
            int n = n0 + wn * 32 + nt * 8 + tig * 2 + (e & 1);
            g_qhh[(size_t)r * CC + n] = __float2half_rn(acc[nt][e]);
        }
}

// ---------------- Output projection: M=16384, K=256, N=256 (BK=32 split-B) ----------------
__global__ void __launch_bounds__(256) k_proj_mma(const float* __restrict__ bp,
                                                  float* __restrict__ out) {
    GEMM_PROLOG32
    int n0 = blockIdx.x * 64, m0 = blockIdx.y * 64;
    float2 rA[4]; __half rBh[8], rBl[8];
    gload_A(g_o, CC, m0, 0, rA);
    gload_B2(g_pwh, g_pwl, CC, 0, n0, rBh, rBl);
    gstore_A(rA, (__half*)smraw);
    gstore_B2(rBh, rBl, (__half*)(smraw + ABYTES), (__half*)(smraw + ABYTES + BBYTES));
    for (int k0 = 0; k0 < CC; k0 += 32) {
        int cur = (k0 >> 5) & 1;
        __syncthreads();
        bool more = (k0 + 32 < CC);
        if (more) {
            gload_A(g_o, CC, m0, k0 + 32, rA);
            gload_B2(g_pwh, g_pwl, CC, k0 + 32, n0, rBh, rBl);
        }
        uint32_t bu = smemU + cur * BUF2;
        mma_step2(bu, bu + ABYTES, bu + ABYTES + BBYTES, acc, wm, wn, aOff, bOff);
        if (more) {
            gstore_A(rA, (__half*)(smraw + (cur ^ 1) * BUF2));
            gstore_B2(rBh, rBl, (__half*)(smraw + (cur ^ 1) * BUF2 + ABYTES),
                      (__half*)(smraw + (cur ^ 1) * BUF2 + ABYTES + BBYTES));
        }
    }
    #pragma unroll
    for (int nt = 0; nt < 4; nt++)
        #pragma unroll
        for (int e = 0; e < 4; e++) {
            int r = m0 + wm * 16 + gid + (e >= 2 ? 8 : 0);
            int n = n0 + wn * 32 + nt * 8 + tig * 2 + (e & 1);
            out[(size_t)r * CC + n] = acc[nt][e] + bp[n];
        }
}

// ---------------- Flash attention (proven, unchanged) ----------------
#define VT_S 130

__global__ void __launch_bounds__(256) k_attn_flash(const int* __restrict__ qlen) {
    __shared__ __half Ks[128 * 40];
    __shared__ __half Vt[32 * VT_S];

    int tid = threadIdx.x;
    int w = tid >> 5, lane = tid & 31;
    int gid = lane >> 2, tig = lane & 3;
    int h = blockIdx.y;
    int q0 = blockIdx.x * 128;

    int l0 = qlen[0], l1 = qlen[1], l2 = qlen[2];
    int b = 0;
    if (q0 >= l0) b = 1;
    if (q0 >= l0 + l1) b = 2;
    if (q0 >= l0 + l1 + l2) b = 3;

    const __half* Kb = g_kh + ((size_t)(b * NHH + h) * NKV) * HDD;
    const __half* Vb = g_vh + ((size_t)(b * NHH + h) * NKV) * HDD;

    uint32_t aQ[2][4];
    {
        const __half* Qp = g_qhh + (size_t)(q0 + w * 16) * CC + h * HDD;
        #pragma unroll
        for (int kc = 0; kc < 2; kc++) {
            int c = kc * 16 + tig * 2;
            aQ[kc][0] = *(const uint32_t*)(Qp + (size_t)gid * CC + c);
            aQ[kc][1] = *(const uint32_t*)(Qp + (size_t)(gid + 8) * CC + c);
            aQ[kc][2] = *(const uint32_t*)(Qp + (size_t)gid * CC + c + 8);
            aQ[kc][3] = *(const uint32_t*)(Qp + (size_t)(gid + 8) * CC + c + 8);
        }
    }

    float o[4][4];
    #pragma unroll
    for (int i = 0; i < 4; i++)
        #pragma unroll
        for (int j = 0; j < 4; j++) o[i][j] = 0.f;
    float mrow[2] = {-1e30f, -1e30f};
    float lsum[2] = {0.f, 0.f};

    for (int kt = 0; kt < 8; kt++) {
        #pragma unroll
        for (int i = 0; i < 8; i++) {
            int idx = tid + i * 256;
            int key = idx >> 4, dp = idx & 15;
            ((uint32_t*)Ks)[key * 20 + dp] =
                *(const uint32_t*)(Kb + (size_t)(kt * 128 + key) * HDD + dp * 2);
        }
        #pragma unroll
        for (int i = 0; i < 8; i++) {
            int idx = tid + i * 256;
            int key = idx >> 4, dp = idx & 15;
            uint32_t u = *(const uint32_t*)(Vb + (size_t)(kt * 128 + key) * HDD + dp * 2);
            __half2 h2 = *(__half2*)&u;
            Vt[(dp * 2) * VT_S + key]     = __low2half(h2);
            Vt[(dp * 2 + 1) * VT_S + key] = __high2half(h2);
        }
        __syncthreads();

        float c[16][4];
        #pragma unroll
        for (int t = 0; t < 16; t++) {
            c[t][0] = c[t][1] = c[t][2] = c[t][3] = 0.f;
            #pragma unroll
            for (int kc = 0; kc < 2; kc++) {
                int cc = kc * 16 + tig * 2;
                uint32_t b0 = *(const uint32_t*)(Ks + (t * 8 + gid) * 40 + cc);
                uint32_t b1 = *(const uint32_t*)(Ks + (t * 8 + gid) * 40 + cc + 8);
                mma16816(c[t], aQ[kc][0], aQ[kc][1], aQ[kc][2], aQ[kc][3], b0, b1);
            }
        }

        float tm0 = -1e30f, tm1 = -1e30f;
        #pragma unroll
        for (int t = 0; t < 16; t++) {
            tm0 = fmaxf(tm0, fmaxf(c[t][0], c[t][1]));
            tm1 = fmaxf(tm1, fmaxf(c[t][2], c[t][3]));
        }
        tm0 = fmaxf(tm0, __shfl_xor_sync(0xffffffffu, tm0, 1));
        tm0 = fmaxf(tm0, __shfl_xor_sync(0xffffffffu, tm0, 2));
        tm1 = fmaxf(tm1, __shfl_xor_sync(0xffffffffu, tm1, 1));
        tm1 = fmaxf(tm1, __shfl_xor_sync(0xffffffffu, tm1, 2));
        float mn0 = fmaxf(mrow[0], tm0);
        float mn1 = fmaxf(mrow[1], tm1);
        float f0 = exp2f((mrow[0] - mn0) * C2E);
        float f1 = exp2f((mrow[1] - mn1) * C2E);
        mrow[0] = mn0; mrow[1] = mn1;
        lsum[0] *= f0; lsum[1] *= f1;
        #pragma unroll
        for (int nt = 0; nt < 4; nt++) {
            o[nt][0] *= f0; o[nt][1] *= f0;
            o[nt][2] *= f1; o[nt][3] *= f1;
        }
        float ps0 = 0.f, ps1 = 0.f;
        uint32_t pf[16][2];
        #pragma unroll
        for (int t = 0; t < 16; t++) {
            float p0 = exp2f((c[t][0] - mn0) * C2E);
            float p1 = exp2f((c[t][1] - mn0) * C2E);
            float p2 = exp2f((c[t][2] - mn1) * C2E);
            float p3 = exp2f((c[t][3] - mn1) * C2E);
            ps0 += p0 + p1;
            ps1 += p2 + p3;
            pf[t][0] = pack2(__float2half_rn(p0), __float2half_rn(p1));
            pf[t][1] = pack2(__float2half_rn(p2), __float2half_rn(p3));
        }
        lsum[0] += ps0;
        lsum[1] += ps1;

        #pragma unroll
        for (int j = 0; j < 8; j++) {
            uint32_t a0 = pf[2 * j][0];
            uint32_t a1 = pf[2 * j][1];
            uint32_t a2 = pf[2 * j + 1][0];
            uint32_t a3 = pf[2 * j + 1][1];
            #pragma unroll
            for (int nt = 0; nt < 4; nt++) {
                int d = nt * 8 + gid;
                uint32_t b0 = *(const uint32_t*)(Vt + d * VT_S + 16 * j + tig * 2);
                uint32_t b1 = *(const uint32_t*)(Vt + d * VT_S + 16 * j + tig * 2 + 8);
                mma16816(o[nt], a0, a1, a2, a3, b0, b1);
            }
        }
        __syncthreads();
    }

    lsum[0] += __shfl_xor_sync(0xffffffffu, lsum[0], 1);
    lsum[0] += __shfl_xor_sync(0xffffffffu, lsum[0], 2);
    lsum[1] += __shfl_xor_sync(0xffffffffu, lsum[1], 1);
    lsum[1] += __shfl_xor_sync(0xffffffffu, lsum[1], 2);

    float i0 = 1.f / lsum[0], i1 = 1.f / lsum[1];
    float* Op = g_o + (size_t)(q0 + w * 16) * CC + h * HDD;
    #pragma unroll
    for (int nt = 0; nt < 4; nt++) {
        int col = nt * 8 + tig * 2;
        float2 v0 = make_float2(o[nt][0] * i0, o[nt][1] * i0);
        float2 v1 = make_float2(o[nt][2] * i1, o[nt][3] * i1);
        *(float2*)(Op + (size_t)gid * CC + col)       = v0;
        *(float2*)(Op + (size_t)(gid + 8) * CC + col) = v1;
    }
}

// ---------------- launch (serial) ----------------
extern "C" void kernel_launch(void* const* d_in, const int* in_sizes, int n_in,
                              void* d_out, int out_size) {
    const float* x      = (const float*)d_in[0];
    const float* q      = (const float*)d_in[1];
    const int*   qlen   = (const int*)  d_in[4];
    const float* w_q    = (const float*)d_in[5];
    const float* w_kv   = (const float*)d_in[6];
    const float* sr_w   = (const float*)d_in[7];
    const float* sr_b   = (const float*)d_in[8];
    const float* ln_g   = (const float*)d_in[9];
    const float* ln_b   = (const float*)d_in[10];
    const float* proj_w = (const float*)d_in[11];
    const float* proj_b = (const float*)d_in[12];
    float* out = (float*)d_out;

    cudaFuncSetAttribute(k_conv_mma,  cudaFuncAttributeMaxDynamicSharedMemorySize, SMEMX);
    cudaFuncSetAttribute(k_kv_mma,    cudaFuncAttributeMaxDynamicSharedMemorySize, SMEMX);
    cudaFuncSetAttribute(k_qproj_mma, cudaFuncAttributeMaxDynamicSharedMemorySize, SMEMX);
    cudaFuncSetAttribute(k_proj_mma,  cudaFuncAttributeMaxDynamicSharedMemorySize, SMEM2);

    __half *wqh, *wkvh, *pwh, *pwl;
    cudaGetSymbolAddress((void**)&wqh,  g_wqh);
    cudaGetSymbolAddress((void**)&wkvh, g_wkvh);
    cudaGetSymbolAddress((void**)&pwh,  g_pwh);
    cudaGetSymbolAddress((void**)&pwl,  g_pwl);

    k_cvt<<<(CC*CC + 255)/256, 256>>>(w_q, wqh, CC*CC);
    k_cvt<<<(CC*2*CC + 255)/256, 256>>>(w_kv, wkvh, CC*2*CC);
    k_split<<<(CC*CC + 255)/256, 256>>>(proj_w, pwh, pwl, CC*CC);
    k_cvt_srw<<<dim3(KCONV/32, CC/32), 256>>>(sr_w);

    k_conv_mma<<<dim3(CC/64, (BB*NKV)/64), 256, SMEMX>>>(x, sr_b);
    k_layernorm<<<(BB*NKV)/8, 256>>>(ln_g, ln_b);
    k_kv_mma<<<dim3((2*CC)/64, (BB*NKV)/64), 256, SMEMX>>>();
    k_qproj_mma<<<dim3(CC/64, TQ/64), 256, SMEMX>>>(q);
    k_attn_flash<<<dim3(TQ/128, NHH), 256>>>(qlen);
    k_proj_mma<<<dim3(CC/64, TQ/64), 256, SMEM2>>>(proj_b, out);
}